// round 1
// baseline (speedup 1.0000x reference)
#include <cuda_runtime.h>
#include <math.h>

#define BB    256
#define AA    512
#define DDW   64
#define NPOS  (AA*DDW)      // 32768 positions per sample
#define NTH   256
#define NITER (NPOS/NTH)    // 128
#define EPSF  1e-5f

// Scratch for x1/x2/x3 activations: [b][a][d][c], c fastest (matches s layout).
__device__ float g_x1[(size_t)BB*NPOS*4];
__device__ float g_x2[(size_t)BB*NPOS*4];
__device__ float g_x3[(size_t)BB*NPOS*4];

__device__ __forceinline__ float4 f4add(float4 a, float4 b){
  return make_float4(a.x+b.x, a.y+b.y, a.z+b.z, a.w+b.w);
}
__device__ __forceinline__ float dot4(float4 w, float4 v){
  return fmaf(w.x, v.x, fmaf(w.y, v.y, fmaf(w.z, v.z, w.w*v.w)));
}
// zero-padded float4 channel load at width position d of one (a) row
__device__ __forceinline__ float4 ld4z(const float* rowBase, int d){
  if ((unsigned)d < (unsigned)DDW)
    return *reinterpret_cast<const float4*>(rowBase + d*4);
  return make_float4(0.f, 0.f, 0.f, 0.f);
}
__device__ __forceinline__ float geluf(float x){
  // exact GELU (approximate=False)
  return 0.5f * x * (1.f + erff(x * 0.70710678118654752440f));
}
// dilated conv weights (O=4, C=4, K=3) -> float4-over-C registers, wk[k][o]
__device__ __forceinline__ void loadConvW(const float* __restrict__ wp, float4 wk[3][4]){
  #pragma unroll
  for (int o = 0; o < 4; o++)
    #pragma unroll
    for (int k = 0; k < 3; k++)
      wk[k][o] = make_float4(wp[o*12 + 0 + k], wp[o*12 + 3 + k],
                             wp[o*12 + 6 + k], wp[o*12 + 9 + k]);
}
__device__ __forceinline__ void loadPwW(const float* __restrict__ wp, float4 pw[4]){
  #pragma unroll
  for (int o = 0; o < 4; o++)
    pw[o] = make_float4(wp[o*4+0], wp[o*4+1], wp[o*4+2], wp[o*4+3]);
}

// block-wide (256 thr) reduction of (sum, sumsq); result broadcast to all threads
__device__ __forceinline__ void blockReduce2(float& s, float& q, volatile float* red){
  #pragma unroll
  for (int off = 16; off > 0; off >>= 1){
    s += __shfl_xor_sync(0xffffffffu, s, off);
    q += __shfl_xor_sync(0xffffffffu, q, off);
  }
  int wp = threadIdx.x >> 5, ln = threadIdx.x & 31;
  __syncthreads();                       // protect scratch from previous use
  if (ln == 0){ red[wp] = s; red[8+wp] = q; }
  __syncthreads();
  if (threadIdx.x == 0){
    float ss = 0.f, qq = 0.f;
    #pragma unroll
    for (int i = 0; i < 8; i++){ ss += red[i]; qq += red[8+i]; }
    red[16] = ss; red[17] = qq;
  }
  __syncthreads();
  s = red[16]; q = red[17];
}

__global__ void __launch_bounds__(NTH, 2)
tcn_kernel(const float* __restrict__ s,    const float* __restrict__ w,
           const float* __restrict__ d1w1, const float* __restrict__ d1w2,
           const float* __restrict__ d2w1, const float* __restrict__ d2w2,
           const float* __restrict__ d3w1, const float* __restrict__ d3w2,
           const float* __restrict__ cw,   const float* __restrict__ c2w,
           const float* __restrict__ c3w,  float* __restrict__ out)
{
  __shared__ float4 sh_tile[NTH];     // 4 KB: staged x-tile for lookahead conv
  __shared__ float  sh_z[16*AA];      // 32 KB: z[o][a] after (1,64) conv
  __shared__ float4 sh_w2[12];        // conv2 weights [k*4+o], float4 over c
  __shared__ float4 sh_w3[12];        // conv3 weights
  __shared__ float  sh_cw[48];        // cw [p*12+c]
  __shared__ float  sh_c3[17];
  __shared__ float  sh_red[18];

  const int b = blockIdx.x, tid = threadIdx.x;
  const float* sb  = s    + (size_t)b*NPOS*4;
  float*       x1b = g_x1 + (size_t)b*NPOS*4;
  float*       x2b = g_x2 + (size_t)b*NPOS*4;
  float*       x3b = g_x3 + (size_t)b*NPOS*4;

  if (tid < 12){
    int k = tid >> 2, o = tid & 3;
    sh_w2[tid] = make_float4(d2w1[o*12+k], d2w1[o*12+3+k], d2w1[o*12+6+k], d2w1[o*12+9+k]);
    sh_w3[tid] = make_float4(d3w1[o*12+k], d3w1[o*12+3+k], d3w1[o*12+6+k], d3w1[o*12+9+k]);
  }
  if (tid < 48) sh_cw[tid] = cw[tid];
  if (tid < 17) sh_c3[tid] = c3w[tid];
  __syncthreads();

  const float invN1  = 1.f/(4.f*(float)NPOS);
  const float invN12 = 1.f/(12.f*(float)NPOS);

  // ================= Pass A: stats of y1 = conv1(s) =================
  float4 w1k[3][4]; loadConvW(d1w1, w1k);
  float sum = 0.f, sq = 0.f;
  for (int it = 0; it < NITER; ++it){
    int pos = it*NTH + tid;
    int a = pos >> 6, d = pos & 63;
    const float* row = sb + a*DDW*4;
    float4 pm = ld4z(row, d-2), pc = ld4z(row, d), pp = ld4z(row, d+2);
    #pragma unroll
    for (int o = 0; o < 4; o++){
      float y = dot4(w1k[0][o], pm) + dot4(w1k[1][o], pc) + dot4(w1k[2][o], pp);
      sum += y; sq = fmaf(y, y, sq);
    }
  }
  blockReduce2(sum, sq, sh_red);
  float m1 = sum*invN1;
  float i1 = rsqrtf(fmaf(-m1, m1, sq*invN1) + EPSF);

  // ===== Pass B: x1 = gelu(pw1(LN(y1))); write x1; stats of y2 = conv2(s+x1) =====
  float4 p1[4]; loadPwW(d1w2, p1);
  sum = 0.f; sq = 0.f;
  for (int it = 0; it < NITER; ++it){
    int pos = it*NTH + tid;
    int a = pos >> 6, d = pos & 63;
    const float* row = sb + a*DDW*4;
    float4 pm = ld4z(row, d-2), pc = ld4z(row, d), pp = ld4z(row, d+2);
    float t[4];
    #pragma unroll
    for (int o = 0; o < 4; o++){
      float y = dot4(w1k[0][o], pm) + dot4(w1k[1][o], pc) + dot4(w1k[2][o], pp);
      t[o] = (y - m1)*i1;
    }
    float4 tv = make_float4(t[0], t[1], t[2], t[3]);
    float4 xv = make_float4(geluf(dot4(p1[0], tv)), geluf(dot4(p1[1], tv)),
                            geluf(dot4(p1[2], tv)), geluf(dot4(p1[3], tv)));
    reinterpret_cast<float4*>(x1b)[pos] = xv;
    __syncthreads();
    sh_tile[tid] = xv;
    __syncthreads();
    float4 z4 = make_float4(0.f, 0.f, 0.f, 0.f);
    float4 tm = (d >= 2)      ? sh_tile[tid-2] : z4;
    float4 tp = (d < DDW-2)   ? sh_tile[tid+2] : z4;
    float4 im = f4add(pm, tm), ic = f4add(pc, xv), ip = f4add(pp, tp);
    #pragma unroll
    for (int o = 0; o < 4; o++){
      float y = dot4(sh_w2[o], im) + dot4(sh_w2[4+o], ic) + dot4(sh_w2[8+o], ip);
      sum += y; sq = fmaf(y, y, sq);
    }
  }
  blockReduce2(sum, sq, sh_red);
  float m2 = sum*invN1;
  float i2 = rsqrtf(fmaf(-m2, m2, sq*invN1) + EPSF);

  // ===== Pass C: x2; write x2; stats of y3 = conv3(s+x1+x2) =====
  float4 w2k[3][4]; loadConvW(d2w1, w2k);
  float4 p2[4];     loadPwW(d2w2, p2);
  sum = 0.f; sq = 0.f;
  for (int it = 0; it < NITER; ++it){
    int pos = it*NTH + tid;
    int a = pos >> 6, d = pos & 63;
    const float* row = sb  + a*DDW*4;
    const float* r1  = x1b + a*DDW*4;
    float4 pm = ld4z(row, d-2), pc = ld4z(row, d), pp = ld4z(row, d+2);
    float4 am = ld4z(r1,  d-2), ac = ld4z(r1,  d), ap = ld4z(r1,  d+2);
    float4 im = f4add(pm, am), ic = f4add(pc, ac), ip = f4add(pp, ap);
    float t[4];
    #pragma unroll
    for (int o = 0; o < 4; o++){
      float y = dot4(w2k[0][o], im) + dot4(w2k[1][o], ic) + dot4(w2k[2][o], ip);
      t[o] = (y - m2)*i2;
    }
    float4 tv = make_float4(t[0], t[1], t[2], t[3]);
    float4 xv = make_float4(geluf(dot4(p2[0], tv)), geluf(dot4(p2[1], tv)),
                            geluf(dot4(p2[2], tv)), geluf(dot4(p2[3], tv)));
    reinterpret_cast<float4*>(x2b)[pos] = xv;
    __syncthreads();
    sh_tile[tid] = xv;
    __syncthreads();
    float4 z4 = make_float4(0.f, 0.f, 0.f, 0.f);
    float4 tm = (d >= 2)    ? sh_tile[tid-2] : z4;
    float4 tp = (d < DDW-2) ? sh_tile[tid+2] : z4;
    float4 jm = f4add(im, tm), jc = f4add(ic, xv), jp = f4add(ip, tp);
    #pragma unroll
    for (int o = 0; o < 4; o++){
      float y = dot4(sh_w3[o], jm) + dot4(sh_w3[4+o], jc) + dot4(sh_w3[8+o], jp);
      sum += y; sq = fmaf(y, y, sq);
    }
  }
  blockReduce2(sum, sq, sh_red);
  float m3 = sum*invN1;
  float i3 = rsqrtf(fmaf(-m3, m3, sq*invN1) + EPSF);

  // ===== Pass D: x3; write x3; concat-LN stats over (x1,x2,x3) =====
  float4 w3k[3][4]; loadConvW(d3w1, w3k);
  float4 p3[4];     loadPwW(d3w2, p3);
  sum = 0.f; sq = 0.f;
  for (int it = 0; it < NITER; ++it){
    int pos = it*NTH + tid;
    int a = pos >> 6, d = pos & 63;
    const float* row = sb  + a*DDW*4;
    const float* r1  = x1b + a*DDW*4;
    const float* r2  = x2b + a*DDW*4;
    float4 pm = ld4z(row, d-2), pc = ld4z(row, d), pp = ld4z(row, d+2);
    float4 am = ld4z(r1,  d-2), ac = ld4z(r1,  d), ap = ld4z(r1,  d+2);
    float4 bm = ld4z(r2,  d-2), bc = ld4z(r2,  d), bp = ld4z(r2,  d+2);
    float4 im = f4add(f4add(pm, am), bm);
    float4 ic = f4add(f4add(pc, ac), bc);
    float4 ip = f4add(f4add(pp, ap), bp);
    float t[4];
    #pragma unroll
    for (int o = 0; o < 4; o++){
      float y = dot4(w3k[0][o], im) + dot4(w3k[1][o], ic) + dot4(w3k[2][o], ip);
      t[o] = (y - m3)*i3;
    }
    float4 tv = make_float4(t[0], t[1], t[2], t[3]);
    float4 xv = make_float4(geluf(dot4(p3[0], tv)), geluf(dot4(p3[1], tv)),
                            geluf(dot4(p3[2], tv)), geluf(dot4(p3[3], tv)));
    reinterpret_cast<float4*>(x3b)[pos] = xv;
    // concat-LN statistics over channels [x1(4), x2(4), x3(4)] at this position
    sum += ac.x+ac.y+ac.z+ac.w + bc.x+bc.y+bc.z+bc.w + xv.x+xv.y+xv.z+xv.w;
    sq  = fmaf(ac.x,ac.x, fmaf(ac.y,ac.y, fmaf(ac.z,ac.z, fmaf(ac.w,ac.w, sq))));
    sq  = fmaf(bc.x,bc.x, fmaf(bc.y,bc.y, fmaf(bc.z,bc.z, fmaf(bc.w,bc.w, sq))));
    sq  = fmaf(xv.x,xv.x, fmaf(xv.y,xv.y, fmaf(xv.z,xv.z, fmaf(xv.w,xv.w, sq))));
  }
  blockReduce2(sum, sq, sh_red);
  float mc   = sum*invN12;
  float icat = rsqrtf(fmaf(-mc, mc, sq*invN12) + EPSF);

  // ===== Pass E: cat-LN -> cw(12->4) -> (1,64) conv c2w -> z[16][A] in SMEM =====
  __syncthreads();
  const int warp = tid >> 5, lane = tid & 31;
  for (int rr = 0; rr < AA/8; ++rr){     // 8 warps, each owns rows warp + 8*rr
    int a = warp + rr*8;
    const float* r1 = x1b + a*DDW*4;
    const float* r2 = x2b + a*DDW*4;
    const float* r3 = x3b + a*DDW*4;
    float acc[16];
    #pragma unroll
    for (int o = 0; o < 16; o++) acc[o] = 0.f;
    #pragma unroll
    for (int h = 0; h < 2; ++h){
      int dd = lane + h*32;
      float4 u1 = reinterpret_cast<const float4*>(r1)[dd];
      float4 u2 = reinterpret_cast<const float4*>(r2)[dd];
      float4 u3 = reinterpret_cast<const float4*>(r3)[dd];
      float u[12] = {
        (u1.x-mc)*icat, (u1.y-mc)*icat, (u1.z-mc)*icat, (u1.w-mc)*icat,
        (u2.x-mc)*icat, (u2.y-mc)*icat, (u2.z-mc)*icat, (u2.w-mc)*icat,
        (u3.x-mc)*icat, (u3.y-mc)*icat, (u3.z-mc)*icat, (u3.w-mc)*icat };
      float v[4];
      #pragma unroll
      for (int p = 0; p < 4; p++){
        float a2 = 0.f;
        #pragma unroll
        for (int c = 0; c < 12; c++) a2 = fmaf(sh_cw[p*12+c], u[c], a2);
        v[p] = a2;
      }
      const float* cb = c2w + dd;          // c2w[o*256 + p*64 + dd]
      #pragma unroll
      for (int o = 0; o < 16; o++){
        float t0 = cb[o*256], t1 = cb[o*256+64], t2 = cb[o*256+128], t3 = cb[o*256+192];
        acc[o] = fmaf(v[0], t0, fmaf(v[1], t1, fmaf(v[2], t2, fmaf(v[3], t3, acc[o]))));
      }
    }
    #pragma unroll
    for (int o = 0; o < 16; o++){
      float vv = acc[o];
      #pragma unroll
      for (int off = 16; off; off >>= 1) vv += __shfl_xor_sync(0xffffffffu, vv, off);
      if (lane == 0) sh_z[o*AA + a] = vv;
    }
  }
  __syncthreads();

  // LN over z (16 x 512)
  float sz = 0.f, qz = 0.f;
  for (int i = tid; i < 16*AA; i += NTH){ float v = sh_z[i]; sz += v; qz = fmaf(v, v, qz); }
  blockReduce2(sz, qz, sh_red);
  const float invN4 = 1.f/(16.f*(float)AA);
  float m4 = sz*invN4;
  float i4 = rsqrtf(fmaf(-m4, m4, qz*invN4) + EPSF);

  // r[a] = sum_o c3w[o]*zn[o,a] + c3w[16]*w[b,a]; then LN over A; write out
  float rv[2]; float sr = 0.f, qr = 0.f;
  #pragma unroll
  for (int j = 0; j < 2; j++){
    int a = tid + j*NTH;
    float r = sh_c3[16]*w[(size_t)b*AA + a];
    #pragma unroll
    for (int o = 0; o < 16; o++)
      r = fmaf(sh_c3[o], (sh_z[o*AA + a] - m4)*i4, r);
    rv[j] = r; sr += r; qr = fmaf(r, r, qr);
  }
  blockReduce2(sr, qr, sh_red);
  float m5 = sr*(1.f/(float)AA);
  float i5 = rsqrtf(fmaf(-m5, m5, qr*(1.f/(float)AA)) + EPSF);
  #pragma unroll
  for (int j = 0; j < 2; j++)
    out[(size_t)b*AA + tid + j*NTH] = (rv[j] - m5)*i5;
}

extern "C" void kernel_launch(void* const* d_in, const int* in_sizes, int n_in,
                              void* d_out, int out_size)
{
  (void)in_sizes; (void)n_in; (void)out_size;
  tcn_kernel<<<BB, NTH>>>(
      (const float*)d_in[0],  (const float*)d_in[1],  (const float*)d_in[2],
      (const float*)d_in[3],  (const float*)d_in[4],  (const float*)d_in[5],
      (const float*)d_in[6],  (const float*)d_in[7],  (const float*)d_in[8],
      (const float*)d_in[9],  (const float*)d_in[10], (float*)d_out);
}

// round 2
// speedup vs baseline: 1.0459x; 1.0459x over previous
#include <cuda_runtime.h>
#include <math.h>

#define BB    256
#define AA    512
#define DDW   64
#define NPOS  (AA*DDW)        // 32768 positions per sample
#define NTH   256
#define CH    8               // chunks per sample
#define ROWS  (AA/CH)         // 64 rows per chunk
#define CITER (ROWS*DDW/NTH)  // 16 iterations per chunk kernel
#define EPSF  1e-5f

// Scratch: x1/x2/x3 activations [b][a][d][c] (c fastest), z [b][a][o] (o fastest)
__device__ float  g_x1[(size_t)BB*NPOS*4];
__device__ float  g_x2[(size_t)BB*NPOS*4];
__device__ float  g_x3[(size_t)BB*NPOS*4];
__device__ float  g_z [(size_t)BB*AA*16];
__device__ float2 g_p1[BB*CH], g_p2[BB*CH], g_p3[BB*CH], g_p4[BB*CH];

__device__ __forceinline__ float4 f4add(float4 a, float4 b){
  return make_float4(a.x+b.x, a.y+b.y, a.z+b.z, a.w+b.w);
}
__device__ __forceinline__ float dot4(float4 w, float4 v){
  return fmaf(w.x, v.x, fmaf(w.y, v.y, fmaf(w.z, v.z, w.w*v.w)));
}
__device__ __forceinline__ float4 ld4z(const float* rowBase, int d){
  if ((unsigned)d < (unsigned)DDW)
    return *reinterpret_cast<const float4*>(rowBase + d*4);
  return make_float4(0.f, 0.f, 0.f, 0.f);
}
__device__ __forceinline__ float geluf(float x){
  return 0.5f * x * (1.f + erff(x * 0.70710678118654752440f));
}
__device__ __forceinline__ void loadConvW(const float* __restrict__ wp, float4 wk[3][4]){
  #pragma unroll
  for (int o = 0; o < 4; o++)
    #pragma unroll
    for (int k = 0; k < 3; k++)
      wk[k][o] = make_float4(wp[o*12 + 0 + k], wp[o*12 + 3 + k],
                             wp[o*12 + 6 + k], wp[o*12 + 9 + k]);
}
__device__ __forceinline__ void loadPwW(const float* __restrict__ wp, float4 pw[4]){
  #pragma unroll
  for (int o = 0; o < 4; o++)
    pw[o] = make_float4(wp[o*4+0], wp[o*4+1], wp[o*4+2], wp[o*4+3]);
}

// Block reduce (sum, sumsq) -> single float2 store by thread 0 (deterministic).
__device__ __forceinline__ void blockReduceStore(float s, float q, float2* dst){
  #pragma unroll
  for (int off = 16; off > 0; off >>= 1){
    s += __shfl_xor_sync(0xffffffffu, s, off);
    q += __shfl_xor_sync(0xffffffffu, q, off);
  }
  __shared__ float red[16];
  int wp = threadIdx.x >> 5, ln = threadIdx.x & 31;
  if (ln == 0){ red[wp] = s; red[8+wp] = q; }
  __syncthreads();
  if (threadIdx.x == 0){
    float ss = 0.f, qq = 0.f;
    #pragma unroll
    for (int i = 0; i < 8; i++){ ss += red[i]; qq += red[8+i]; }
    *dst = make_float2(ss, qq);
  }
}

// Every thread deterministically folds the CH partials into (mean, invstd).
__device__ __forceinline__ void finalizeStats(const float2* __restrict__ part, int b,
                                              float invN, float& m, float& inv){
  float s = 0.f, q = 0.f;
  #pragma unroll
  for (int i = 0; i < CH; i++){
    float2 p = __ldg(&part[b*CH + i]);
    s += p.x; q += p.y;
  }
  m = s*invN;
  inv = rsqrtf(fmaf(-m, m, q*invN) + EPSF);
}

// Block reduce with broadcast to all threads (for the per-sample finale).
__device__ __forceinline__ void blockReduce2(float& s, float& q, volatile float* red){
  #pragma unroll
  for (int off = 16; off > 0; off >>= 1){
    s += __shfl_xor_sync(0xffffffffu, s, off);
    q += __shfl_xor_sync(0xffffffffu, q, off);
  }
  int wp = threadIdx.x >> 5, ln = threadIdx.x & 31;
  __syncthreads();
  if (ln == 0){ red[wp] = s; red[8+wp] = q; }
  __syncthreads();
  if (threadIdx.x == 0){
    float ss = 0.f, qq = 0.f;
    #pragma unroll
    for (int i = 0; i < 8; i++){ ss += red[i]; qq += red[8+i]; }
    red[16] = ss; red[17] = qq;
  }
  __syncthreads();
  s = red[16]; q = red[17];
}

#define INV_N1  (1.f/(4.f*(float)NPOS))
#define INV_N12 (1.f/(12.f*(float)NPOS))

// ============ K0: stats of y1 = conv1(s) ============
__global__ void __launch_bounds__(NTH)
k_statsA(const float* __restrict__ s, const float* __restrict__ d1w1)
{
  const int b = blockIdx.x >> 3, chk = blockIdx.x & 7;
  const float* sb = s + (size_t)b*NPOS*4 + (size_t)chk*ROWS*DDW*4;
  float4 wk[3][4]; loadConvW(d1w1, wk);
  float sum = 0.f, sq = 0.f;
  for (int it = 0; it < CITER; ++it){
    int pos = it*NTH + threadIdx.x;
    int a = pos >> 6, d = pos & 63;
    const float* row = sb + a*DDW*4;
    float4 pm = ld4z(row, d-2), pc = ld4z(row, d), pp = ld4z(row, d+2);
    #pragma unroll
    for (int o = 0; o < 4; o++){
      float y = dot4(wk[0][o], pm) + dot4(wk[1][o], pc) + dot4(wk[2][o], pp);
      sum += y; sq = fmaf(y, y, sq);
    }
  }
  blockReduceStore(sum, sq, &g_p1[blockIdx.x]);
}

// ============ K1: x1 = gelu(pw1(LN(y1))); write x1; stats of y2 = conv2(s+x1) ============
__global__ void __launch_bounds__(NTH)
k_passB(const float* __restrict__ s, const float* __restrict__ d1w1,
        const float* __restrict__ d1w2, const float* __restrict__ d2w1)
{
  __shared__ float4 sh_tile[NTH];
  __shared__ float4 sh_w2[12];
  const int b = blockIdx.x >> 3, chk = blockIdx.x & 7, tid = threadIdx.x;
  const size_t off = (size_t)b*NPOS*4 + (size_t)chk*ROWS*DDW*4;
  const float* sb  = s + off;
  float*       x1b = g_x1 + off;
  if (tid < 12){
    int k = tid >> 2, o = tid & 3;
    sh_w2[tid] = make_float4(d2w1[o*12+k], d2w1[o*12+3+k], d2w1[o*12+6+k], d2w1[o*12+9+k]);
  }
  float4 w1k[3][4]; loadConvW(d1w1, w1k);
  float4 p1[4];     loadPwW(d1w2, p1);
  float m1, i1; finalizeStats(g_p1, b, INV_N1, m1, i1);
  __syncthreads();

  float sum = 0.f, sq = 0.f;
  for (int it = 0; it < CITER; ++it){
    int pos = it*NTH + tid;
    int a = pos >> 6, d = pos & 63;
    const float* row = sb + a*DDW*4;
    float4 pm = ld4z(row, d-2), pc = ld4z(row, d), pp = ld4z(row, d+2);
    float t[4];
    #pragma unroll
    for (int o = 0; o < 4; o++){
      float y = dot4(w1k[0][o], pm) + dot4(w1k[1][o], pc) + dot4(w1k[2][o], pp);
      t[o] = (y - m1)*i1;
    }
    float4 tv = make_float4(t[0], t[1], t[2], t[3]);
    float4 xv = make_float4(geluf(dot4(p1[0], tv)), geluf(dot4(p1[1], tv)),
                            geluf(dot4(p1[2], tv)), geluf(dot4(p1[3], tv)));
    reinterpret_cast<float4*>(x1b)[pos] = xv;
    __syncthreads();
    sh_tile[tid] = xv;
    __syncthreads();
    float4 z4 = make_float4(0.f, 0.f, 0.f, 0.f);
    float4 tm = (d >= 2)      ? sh_tile[tid-2] : z4;
    float4 tp = (d < DDW-2)   ? sh_tile[tid+2] : z4;
    float4 im = f4add(pm, tm), ic = f4add(pc, xv), ip = f4add(pp, tp);
    #pragma unroll
    for (int o = 0; o < 4; o++){
      float y = dot4(sh_w2[o], im) + dot4(sh_w2[4+o], ic) + dot4(sh_w2[8+o], ip);
      sum += y; sq = fmaf(y, y, sq);
    }
  }
  blockReduceStore(sum, sq, &g_p2[blockIdx.x]);
}

// ============ K2: x2; write x2; stats of y3 = conv3(s+x1+x2) ============
__global__ void __launch_bounds__(NTH)
k_passC(const float* __restrict__ s, const float* __restrict__ d2w1,
        const float* __restrict__ d2w2, const float* __restrict__ d3w1)
{
  __shared__ float4 sh_tile[NTH];
  __shared__ float4 sh_w3[12];
  const int b = blockIdx.x >> 3, chk = blockIdx.x & 7, tid = threadIdx.x;
  const size_t off = (size_t)b*NPOS*4 + (size_t)chk*ROWS*DDW*4;
  const float* sb  = s + off;
  const float* x1b = g_x1 + off;
  float*       x2b = g_x2 + off;
  if (tid < 12){
    int k = tid >> 2, o = tid & 3;
    sh_w3[tid] = make_float4(d3w1[o*12+k], d3w1[o*12+3+k], d3w1[o*12+6+k], d3w1[o*12+9+k]);
  }
  float4 w2k[3][4]; loadConvW(d2w1, w2k);
  float4 p2[4];     loadPwW(d2w2, p2);
  float m2, i2; finalizeStats(g_p2, b, INV_N1, m2, i2);
  __syncthreads();

  float sum = 0.f, sq = 0.f;
  for (int it = 0; it < CITER; ++it){
    int pos = it*NTH + tid;
    int a = pos >> 6, d = pos & 63;
    const float* row = sb  + a*DDW*4;
    const float* r1  = x1b + a*DDW*4;
    float4 pm = ld4z(row, d-2), pc = ld4z(row, d), pp = ld4z(row, d+2);
    float4 am = ld4z(r1,  d-2), ac = ld4z(r1,  d), ap = ld4z(r1,  d+2);
    float4 im = f4add(pm, am), ic = f4add(pc, ac), ip = f4add(pp, ap);
    float t[4];
    #pragma unroll
    for (int o = 0; o < 4; o++){
      float y = dot4(w2k[0][o], im) + dot4(w2k[1][o], ic) + dot4(w2k[2][o], ip);
      t[o] = (y - m2)*i2;
    }
    float4 tv = make_float4(t[0], t[1], t[2], t[3]);
    float4 xv = make_float4(geluf(dot4(p2[0], tv)), geluf(dot4(p2[1], tv)),
                            geluf(dot4(p2[2], tv)), geluf(dot4(p2[3], tv)));
    reinterpret_cast<float4*>(x2b)[pos] = xv;
    __syncthreads();
    sh_tile[tid] = xv;
    __syncthreads();
    float4 z4 = make_float4(0.f, 0.f, 0.f, 0.f);
    float4 tm = (d >= 2)    ? sh_tile[tid-2] : z4;
    float4 tp = (d < DDW-2) ? sh_tile[tid+2] : z4;
    float4 jm = f4add(im, tm), jc = f4add(ic, xv), jp = f4add(ip, tp);
    #pragma unroll
    for (int o = 0; o < 4; o++){
      float y = dot4(sh_w3[o], jm) + dot4(sh_w3[4+o], jc) + dot4(sh_w3[8+o], jp);
      sum += y; sq = fmaf(y, y, sq);
    }
  }
  blockReduceStore(sum, sq, &g_p3[blockIdx.x]);
}

// ============ K3: x3; write x3; concat-LN stats over (x1,x2,x3) ============
__global__ void __launch_bounds__(NTH)
k_passD(const float* __restrict__ s, const float* __restrict__ d3w1,
        const float* __restrict__ d3w2)
{
  const int b = blockIdx.x >> 3, chk = blockIdx.x & 7, tid = threadIdx.x;
  const size_t off = (size_t)b*NPOS*4 + (size_t)chk*ROWS*DDW*4;
  const float* sb  = s + off;
  const float* x1b = g_x1 + off;
  const float* x2b = g_x2 + off;
  float*       x3b = g_x3 + off;
  float4 w3k[3][4]; loadConvW(d3w1, w3k);
  float4 p3[4];     loadPwW(d3w2, p3);
  float m3, i3; finalizeStats(g_p3, b, INV_N1, m3, i3);

  float sum = 0.f, sq = 0.f;
  for (int it = 0; it < CITER; ++it){
    int pos = it*NTH + tid;
    int a = pos >> 6, d = pos & 63;
    const float* row = sb  + a*DDW*4;
    const float* r1  = x1b + a*DDW*4;
    const float* r2  = x2b + a*DDW*4;
    float4 pm = ld4z(row, d-2), pc = ld4z(row, d), pp = ld4z(row, d+2);
    float4 am = ld4z(r1,  d-2), ac = ld4z(r1,  d), ap = ld4z(r1,  d+2);
    float4 bm = ld4z(r2,  d-2), bc = ld4z(r2,  d), bp = ld4z(r2,  d+2);
    float4 im = f4add(f4add(pm, am), bm);
    float4 ic = f4add(f4add(pc, ac), bc);
    float4 ip = f4add(f4add(pp, ap), bp);
    float t[4];
    #pragma unroll
    for (int o = 0; o < 4; o++){
      float y = dot4(w3k[0][o], im) + dot4(w3k[1][o], ic) + dot4(w3k[2][o], ip);
      t[o] = (y - m3)*i3;
    }
    float4 tv = make_float4(t[0], t[1], t[2], t[3]);
    float4 xv = make_float4(geluf(dot4(p3[0], tv)), geluf(dot4(p3[1], tv)),
                            geluf(dot4(p3[2], tv)), geluf(dot4(p3[3], tv)));
    reinterpret_cast<float4*>(x3b)[pos] = xv;
    sum += ac.x+ac.y+ac.z+ac.w + bc.x+bc.y+bc.z+bc.w + xv.x+xv.y+xv.z+xv.w;
    sq  = fmaf(ac.x,ac.x, fmaf(ac.y,ac.y, fmaf(ac.z,ac.z, fmaf(ac.w,ac.w, sq))));
    sq  = fmaf(bc.x,bc.x, fmaf(bc.y,bc.y, fmaf(bc.z,bc.z, fmaf(bc.w,bc.w, sq))));
    sq  = fmaf(xv.x,xv.x, fmaf(xv.y,xv.y, fmaf(xv.z,xv.z, fmaf(xv.w,xv.w, sq))));
  }
  blockReduceStore(sum, sq, &g_p4[blockIdx.x]);
}

// ============ K4: cat-LN -> cw(12->4) -> (1,64) conv -> z[b][a][16] ============
__global__ void __launch_bounds__(NTH)
k_convZ(const float* __restrict__ cw, const float* __restrict__ c2w)
{
  __shared__ float sh_c2[16*4*64];   // [o*256 + p*64 + d], 16 KB
  __shared__ float sh_cw[48];
  const int b = blockIdx.x >> 3, chk = blockIdx.x & 7, tid = threadIdx.x;
  for (int i = tid; i < 4096; i += NTH) sh_c2[i] = c2w[i];
  if (tid < 48) sh_cw[tid] = cw[tid];
  float mc, icat; finalizeStats(g_p4, b, INV_N12, mc, icat);
  __syncthreads();

  const size_t off = (size_t)b*NPOS*4 + (size_t)chk*ROWS*DDW*4;
  const float* r1b = g_x1 + off;
  const float* r2b = g_x2 + off;
  const float* r3b = g_x3 + off;
  const int warp = tid >> 5, lane = tid & 31;

  for (int rr = 0; rr < ROWS/8; ++rr){
    int al = warp + rr*8;            // local row within chunk
    const float* r1 = r1b + al*DDW*4;
    const float* r2 = r2b + al*DDW*4;
    const float* r3 = r3b + al*DDW*4;
    float acc[16];
    #pragma unroll
    for (int o = 0; o < 16; o++) acc[o] = 0.f;
    #pragma unroll
    for (int h = 0; h < 2; ++h){
      int dd = lane + h*32;
      float4 u1 = reinterpret_cast<const float4*>(r1)[dd];
      float4 u2 = reinterpret_cast<const float4*>(r2)[dd];
      float4 u3 = reinterpret_cast<const float4*>(r3)[dd];
      float u[12] = {
        (u1.x-mc)*icat, (u1.y-mc)*icat, (u1.z-mc)*icat, (u1.w-mc)*icat,
        (u2.x-mc)*icat, (u2.y-mc)*icat, (u2.z-mc)*icat, (u2.w-mc)*icat,
        (u3.x-mc)*icat, (u3.y-mc)*icat, (u3.z-mc)*icat, (u3.w-mc)*icat };
      float v[4];
      #pragma unroll
      for (int p = 0; p < 4; p++){
        float a2 = 0.f;
        #pragma unroll
        for (int c = 0; c < 12; c++) a2 = fmaf(sh_cw[p*12+c], u[c], a2);
        v[p] = a2;
      }
      const float* cb = sh_c2 + dd;
      #pragma unroll
      for (int o = 0; o < 16; o++){
        float t0 = cb[o*256], t1 = cb[o*256+64], t2 = cb[o*256+128], t3 = cb[o*256+192];
        acc[o] = fmaf(v[0], t0, fmaf(v[1], t1, fmaf(v[2], t2, fmaf(v[3], t3, acc[o]))));
      }
    }
    #pragma unroll
    for (int o = 0; o < 16; o++){
      #pragma unroll
      for (int off2 = 16; off2; off2 >>= 1)
        acc[o] += __shfl_xor_sync(0xffffffffu, acc[o], off2);
    }
    if (lane == 0){
      int ag = chk*ROWS + al;
      float4* dst = reinterpret_cast<float4*>(g_z + ((size_t)b*AA + ag)*16);
      dst[0] = make_float4(acc[0],  acc[1],  acc[2],  acc[3]);
      dst[1] = make_float4(acc[4],  acc[5],  acc[6],  acc[7]);
      dst[2] = make_float4(acc[8],  acc[9],  acc[10], acc[11]);
      dst[3] = make_float4(acc[12], acc[13], acc[14], acc[15]);
    }
  }
}

// ============ K5: LN(z) -> +w -> 1x1(17->1) -> LN -> out ============
__global__ void __launch_bounds__(NTH)
k_final(const float* __restrict__ w, const float* __restrict__ c3w,
        float* __restrict__ out)
{
  __shared__ float sh_z[AA*17];      // padded stride 17 to avoid bank conflicts
  __shared__ float sh_red[18];
  __shared__ float sh_c3[17];
  const int b = blockIdx.x, tid = threadIdx.x;
  if (tid < 17) sh_c3[tid] = c3w[tid];

  const float4* zsrc = reinterpret_cast<const float4*>(g_z + (size_t)b*AA*16);
  float sz = 0.f, qz = 0.f;
  for (int i = tid; i < AA*4; i += NTH){       // i indexes float4; 4 per row
    float4 v = zsrc[i];
    int a = i >> 2, o4 = (i & 3)*4;
    float* dst = sh_z + a*17 + o4;
    dst[0] = v.x; dst[1] = v.y; dst[2] = v.z; dst[3] = v.w;
    sz += v.x+v.y+v.z+v.w;
    qz = fmaf(v.x,v.x, fmaf(v.y,v.y, fmaf(v.z,v.z, fmaf(v.w,v.w, qz))));
  }
  blockReduce2(sz, qz, sh_red);
  const float invN4 = 1.f/(16.f*(float)AA);
  float m4 = sz*invN4;
  float i4 = rsqrtf(fmaf(-m4, m4, qz*invN4) + EPSF);

  float rv[2]; float sr = 0.f, qr = 0.f;
  #pragma unroll
  for (int j = 0; j < 2; j++){
    int a = tid + j*NTH;
    float r = sh_c3[16]*w[(size_t)b*AA + a];
    const float* zr = sh_z + a*17;
    #pragma unroll
    for (int o = 0; o < 16; o++)
      r = fmaf(sh_c3[o], (zr[o] - m4)*i4, r);
    rv[j] = r; sr += r; qr = fmaf(r, r, qr);
  }
  blockReduce2(sr, qr, sh_red);
  float m5 = sr*(1.f/(float)AA);
  float i5 = rsqrtf(fmaf(-m5, m5, qr*(1.f/(float)AA)) + EPSF);
  #pragma unroll
  for (int j = 0; j < 2; j++)
    out[(size_t)b*AA + tid + j*NTH] = (rv[j] - m5)*i5;
}

extern "C" void kernel_launch(void* const* d_in, const int* in_sizes, int n_in,
                              void* d_out, int out_size)
{
  (void)in_sizes; (void)n_in; (void)out_size;
  const float* s    = (const float*)d_in[0];
  const float* w    = (const float*)d_in[1];
  const float* d1w1 = (const float*)d_in[2];
  const float* d1w2 = (const float*)d_in[3];
  const float* d2w1 = (const float*)d_in[4];
  const float* d2w2 = (const float*)d_in[5];
  const float* d3w1 = (const float*)d_in[6];
  const float* d3w2 = (const float*)d_in[7];
  const float* cw   = (const float*)d_in[8];
  const float* c2w  = (const float*)d_in[9];
  const float* c3w  = (const float*)d_in[10];
  float* out = (float*)d_out;

  k_statsA<<<BB*CH, NTH>>>(s, d1w1);
  k_passB <<<BB*CH, NTH>>>(s, d1w1, d1w2, d2w1);
  k_passC <<<BB*CH, NTH>>>(s, d2w1, d2w2, d3w1);
  k_passD <<<BB*CH, NTH>>>(s, d3w1, d3w2);
  k_convZ <<<BB*CH, NTH>>>(cw, c2w);
  k_final <<<BB,    NTH>>>(w, c3w, out);
}

// round 3
// speedup vs baseline: 1.3910x; 1.3300x over previous
#include <cuda_runtime.h>
#include <math.h>

#define BB    256
#define AA    512
#define DDW   64
#define NPOS  (AA*DDW)        // 32768 positions per sample
#define NTH   256
#define CH    8               // chunks per sample
#define ROWS  (AA/CH)         // 64 rows per chunk
#define EPSF  1e-5f

// Scratch: x1/x2 activations [b][a][d][c] (c fastest); zraw [b][a][o]
__device__ float  g_x1[(size_t)BB*NPOS*4];
__device__ float  g_x2[(size_t)BB*NPOS*4];
__device__ float  g_z [(size_t)BB*AA*16];
__device__ float2 g_p1[BB*CH], g_p2[BB*CH], g_p3[BB*CH], g_p4[BB*CH];

__device__ __forceinline__ float4 f4add(float4 a, float4 b){
  return make_float4(a.x+b.x, a.y+b.y, a.z+b.z, a.w+b.w);
}
__device__ __forceinline__ float dot4(float4 w, float4 v){
  return fmaf(w.x, v.x, fmaf(w.y, v.y, fmaf(w.z, v.z, w.w*v.w)));
}
__device__ __forceinline__ float4 ld4z(const float* rowBase, int d){
  if ((unsigned)d < (unsigned)DDW)
    return *reinterpret_cast<const float4*>(rowBase + d*4);
  return make_float4(0.f, 0.f, 0.f, 0.f);
}
__device__ __forceinline__ float geluf(float x){
  return 0.5f * x * (1.f + erff(x * 0.70710678118654752440f));
}
__device__ __forceinline__ void loadConvW(const float* __restrict__ wp, float4 wk[3][4]){
  #pragma unroll
  for (int o = 0; o < 4; o++)
    #pragma unroll
    for (int k = 0; k < 3; k++)
      wk[k][o] = make_float4(wp[o*12 + 0 + k], wp[o*12 + 3 + k],
                             wp[o*12 + 6 + k], wp[o*12 + 9 + k]);
}
__device__ __forceinline__ float4 shflup4(float4 v){
  float4 r;
  r.x = __shfl_up_sync(0xffffffffu, v.x, 1);
  r.y = __shfl_up_sync(0xffffffffu, v.y, 1);
  r.z = __shfl_up_sync(0xffffffffu, v.z, 1);
  r.w = __shfl_up_sync(0xffffffffu, v.w, 1);
  return r;
}
__device__ __forceinline__ float4 shfldn4(float4 v){
  float4 r;
  r.x = __shfl_down_sync(0xffffffffu, v.x, 1);
  r.y = __shfl_down_sync(0xffffffffu, v.y, 1);
  r.z = __shfl_down_sync(0xffffffffu, v.z, 1);
  r.w = __shfl_down_sync(0xffffffffu, v.w, 1);
  return r;
}

__device__ __forceinline__ void blockReduceStore(float s, float q, float2* dst){
  #pragma unroll
  for (int off = 16; off > 0; off >>= 1){
    s += __shfl_xor_sync(0xffffffffu, s, off);
    q += __shfl_xor_sync(0xffffffffu, q, off);
  }
  __shared__ float red[16];
  int wp = threadIdx.x >> 5, ln = threadIdx.x & 31;
  if (ln == 0){ red[wp] = s; red[8+wp] = q; }
  __syncthreads();
  if (threadIdx.x == 0){
    float ss = 0.f, qq = 0.f;
    #pragma unroll
    for (int i = 0; i < 8; i++){ ss += red[i]; qq += red[8+i]; }
    *dst = make_float2(ss, qq);
  }
}

__device__ __forceinline__ void finalizeStats(const float2* __restrict__ part, int b,
                                              float invN, float& m, float& inv){
  float s = 0.f, q = 0.f;
  #pragma unroll
  for (int i = 0; i < CH; i++){
    float2 p = __ldg(&part[b*CH + i]);
    s += p.x; q += p.y;
  }
  m = s*invN;
  inv = rsqrtf(fmaf(-m, m, q*invN) + EPSF);
}

__device__ __forceinline__ void blockReduce2(float& s, float& q, volatile float* red){
  #pragma unroll
  for (int off = 16; off > 0; off >>= 1){
    s += __shfl_xor_sync(0xffffffffu, s, off);
    q += __shfl_xor_sync(0xffffffffu, q, off);
  }
  int wp = threadIdx.x >> 5, ln = threadIdx.x & 31;
  __syncthreads();
  if (ln == 0){ red[wp] = s; red[8+wp] = q; }
  __syncthreads();
  if (threadIdx.x == 0){
    float ss = 0.f, qq = 0.f;
    #pragma unroll
    for (int i = 0; i < 8; i++){ ss += red[i]; qq += red[8+i]; }
    red[16] = ss; red[17] = qq;
  }
  __syncthreads();
  s = red[16]; q = red[17];
}

#define INV_N1  (1.f/(4.f*(float)NPOS))
#define INV_N12 (1.f/(12.f*(float)NPOS))

// ============ K0: stats of y1 = conv1(s) ============
__global__ void __launch_bounds__(NTH, 2)
k_statsA(const float* __restrict__ s, const float* __restrict__ d1w1)
{
  const int b = blockIdx.x >> 3, chk = blockIdx.x & 7;
  const int lane = threadIdx.x & 31, warp = threadIdx.x >> 5;
  const int i = lane & 15, e = lane >> 4;
  const int t0 = 4*i + e - 2;                  // leftmost tap
  const float* sb = s + (size_t)b*NPOS*4 + (size_t)chk*ROWS*DDW*4;
  float4 wk[3][4]; loadConvW(d1w1, wk);
  float sum = 0.f, sq = 0.f;
  for (int r = 0; r < 8; ++r){
    int a = warp + 8*r;
    const float* row = sb + a*DDW*4;
    float4 S[4];
    #pragma unroll
    for (int k = 0; k < 4; k++) S[k] = ld4z(row, t0 + 2*k);
    #pragma unroll
    for (int j = 0; j < 2; j++){
      #pragma unroll
      for (int o = 0; o < 4; o++){
        float y = dot4(wk[0][o], S[j]) + dot4(wk[1][o], S[j+1]) + dot4(wk[2][o], S[j+2]);
        sum += y; sq = fmaf(y, y, sq);
      }
    }
  }
  blockReduceStore(sum, sq, &g_p1[blockIdx.x]);
}

// ============ K1: x1 = gelu(pw1(LN(y1))); write x1; stats of y2 = conv2(s+x1) ============
__global__ void __launch_bounds__(NTH, 2)
k_passB(const float* __restrict__ s, const float* __restrict__ d1w1,
        const float* __restrict__ d1w2, const float* __restrict__ d2w1)
{
  __shared__ float4 sh_w2[12];   // stats conv weights [k*4+o]
  __shared__ float4 sh_p1[4];    // pointwise weights
  const int b = blockIdx.x >> 3, chk = blockIdx.x & 7, tid = threadIdx.x;
  const int lane = tid & 31, warp = tid >> 5;
  const int i = lane & 15, e = lane >> 4;
  const int t0 = 4*i + e - 2;
  const size_t off = (size_t)b*NPOS*4 + (size_t)chk*ROWS*DDW*4;
  const float* sb  = s + off;
  float*       x1b = g_x1 + off;
  if (tid < 12){
    int k = tid >> 2, o = tid & 3;
    sh_w2[tid] = make_float4(d2w1[o*12+k], d2w1[o*12+3+k], d2w1[o*12+6+k], d2w1[o*12+9+k]);
  }
  if (tid < 4) sh_p1[tid] = make_float4(d1w2[tid*4+0], d1w2[tid*4+1], d1w2[tid*4+2], d1w2[tid*4+3]);
  float4 w1k[3][4]; loadConvW(d1w1, w1k);
  float m1, i1; finalizeStats(g_p1, b, INV_N1, m1, i1);
  __syncthreads();

  float sum = 0.f, sq = 0.f;
  for (int r = 0; r < 8; ++r){
    int a = warp + 8*r;
    const float* row = sb + a*DDW*4;
    float4 S[4];
    #pragma unroll
    for (int k = 0; k < 4; k++) S[k] = ld4z(row, t0 + 2*k);
    float4 xv[2];
    #pragma unroll
    for (int j = 0; j < 2; j++){
      float t[4];
      #pragma unroll
      for (int o = 0; o < 4; o++){
        float y = dot4(w1k[0][o], S[j]) + dot4(w1k[1][o], S[j+1]) + dot4(w1k[2][o], S[j+2]);
        t[o] = (y - m1)*i1;
      }
      float4 tv = make_float4(t[0], t[1], t[2], t[3]);
      xv[j] = make_float4(geluf(dot4(sh_p1[0], tv)), geluf(dot4(sh_p1[1], tv)),
                          geluf(dot4(sh_p1[2], tv)), geluf(dot4(sh_p1[3], tv)));
      reinterpret_cast<float4*>(x1b)[a*DDW + t0 + 2 + 2*j] = xv[j];
    }
    float4 z4 = make_float4(0.f,0.f,0.f,0.f);
    float4 xn0 = shflup4(xv[1]); if (i == 0)  xn0 = z4;
    float4 xn3 = shfldn4(xv[0]); if (i == 15) xn3 = z4;
    float4 XN[4] = {xn0, xv[0], xv[1], xn3};
    #pragma unroll
    for (int j = 0; j < 2; j++){
      float4 U0 = f4add(S[j],   XN[j]);
      float4 U1 = f4add(S[j+1], XN[j+1]);
      float4 U2 = f4add(S[j+2], XN[j+2]);
      #pragma unroll
      for (int o = 0; o < 4; o++){
        float y = dot4(sh_w2[o], U0) + dot4(sh_w2[4+o], U1) + dot4(sh_w2[8+o], U2);
        sum += y; sq = fmaf(y, y, sq);
      }
    }
  }
  blockReduceStore(sum, sq, &g_p2[blockIdx.x]);
}

// ============ K2: x2; write x2; stats of y3 = conv3(s+x1+x2) ============
__global__ void __launch_bounds__(NTH, 2)
k_passC(const float* __restrict__ s, const float* __restrict__ d2w1,
        const float* __restrict__ d2w2, const float* __restrict__ d3w1)
{
  __shared__ float4 sh_w3[12];
  __shared__ float4 sh_p2[4];
  const int b = blockIdx.x >> 3, chk = blockIdx.x & 7, tid = threadIdx.x;
  const int lane = tid & 31, warp = tid >> 5;
  const int i = lane & 15, e = lane >> 4;
  const int t0 = 4*i + e - 2;
  const size_t off = (size_t)b*NPOS*4 + (size_t)chk*ROWS*DDW*4;
  const float* sb  = s + off;
  const float* x1b = g_x1 + off;
  float*       x2b = g_x2 + off;
  if (tid < 12){
    int k = tid >> 2, o = tid & 3;
    sh_w3[tid] = make_float4(d3w1[o*12+k], d3w1[o*12+3+k], d3w1[o*12+6+k], d3w1[o*12+9+k]);
  }
  if (tid < 4) sh_p2[tid] = make_float4(d2w2[tid*4+0], d2w2[tid*4+1], d2w2[tid*4+2], d2w2[tid*4+3]);
  float4 w2k[3][4]; loadConvW(d2w1, w2k);
  float m2, i2; finalizeStats(g_p2, b, INV_N1, m2, i2);
  __syncthreads();

  float sum = 0.f, sq = 0.f;
  for (int r = 0; r < 8; ++r){
    int a = warp + 8*r;
    const float* row = sb  + a*DDW*4;
    const float* r1  = x1b + a*DDW*4;
    float4 I[4];
    #pragma unroll
    for (int k = 0; k < 4; k++)
      I[k] = f4add(ld4z(row, t0 + 2*k), ld4z(r1, t0 + 2*k));
    float4 xv[2];
    #pragma unroll
    for (int j = 0; j < 2; j++){
      float t[4];
      #pragma unroll
      for (int o = 0; o < 4; o++){
        float y = dot4(w2k[0][o], I[j]) + dot4(w2k[1][o], I[j+1]) + dot4(w2k[2][o], I[j+2]);
        t[o] = (y - m2)*i2;
      }
      float4 tv = make_float4(t[0], t[1], t[2], t[3]);
      xv[j] = make_float4(geluf(dot4(sh_p2[0], tv)), geluf(dot4(sh_p2[1], tv)),
                          geluf(dot4(sh_p2[2], tv)), geluf(dot4(sh_p2[3], tv)));
      reinterpret_cast<float4*>(x2b)[a*DDW + t0 + 2 + 2*j] = xv[j];
    }
    float4 z4 = make_float4(0.f,0.f,0.f,0.f);
    float4 xn0 = shflup4(xv[1]); if (i == 0)  xn0 = z4;
    float4 xn3 = shfldn4(xv[0]); if (i == 15) xn3 = z4;
    float4 XN[4] = {xn0, xv[0], xv[1], xn3};
    #pragma unroll
    for (int j = 0; j < 2; j++){
      float4 U0 = f4add(I[j],   XN[j]);
      float4 U1 = f4add(I[j+1], XN[j+1]);
      float4 U2 = f4add(I[j+2], XN[j+2]);
      #pragma unroll
      for (int o = 0; o < 4; o++){
        float y = dot4(sh_w3[o], U0) + dot4(sh_w3[4+o], U1) + dot4(sh_w3[8+o], U2);
        sum += y; sq = fmaf(y, y, sq);
      }
    }
  }
  blockReduceStore(sum, sq, &g_p3[blockIdx.x]);
}

// ============ K3: x3 (regs only) + zraw = c2w*cw*xcat (unnormalized) + cat stats ============
__global__ void __launch_bounds__(NTH, 2)
k_passD(const float* __restrict__ s, const float* __restrict__ d3w1,
        const float* __restrict__ d3w2, const float* __restrict__ cw,
        const float* __restrict__ c2w)
{
  __shared__ float  sh_c2[16*4*64];   // [o*256 + p*64 + d]
  __shared__ float  sh_cw[48];        // [p*12+c]
  __shared__ float4 sh_w3[12];
  __shared__ float4 sh_p3[4];
  const int b = blockIdx.x >> 3, chk = blockIdx.x & 7, tid = threadIdx.x;
  const int lane = tid & 31, warp = tid >> 5;
  const int i = lane & 15, e = lane >> 4;
  const int t0 = 4*i + e - 2;
  const size_t off = (size_t)b*NPOS*4 + (size_t)chk*ROWS*DDW*4;
  const float* sb  = s + off;
  const float* x1b = g_x1 + off;
  const float* x2b = g_x2 + off;
  for (int k = tid; k < 4096; k += NTH) sh_c2[k] = c2w[k];
  if (tid < 48) sh_cw[tid] = cw[tid];
  if (tid < 12){
    int k = tid >> 2, o = tid & 3;
    sh_w3[tid] = make_float4(d3w1[o*12+k], d3w1[o*12+3+k], d3w1[o*12+6+k], d3w1[o*12+9+k]);
  }
  if (tid < 4) sh_p3[tid] = make_float4(d3w2[tid*4+0], d3w2[tid*4+1], d3w2[tid*4+2], d3w2[tid*4+3]);
  float m3, i3; finalizeStats(g_p3, b, INV_N1, m3, i3);
  __syncthreads();

  float sum = 0.f, sq = 0.f;
  for (int r = 0; r < 8; ++r){
    int a = warp + 8*r;
    const float* row = sb  + a*DDW*4;
    const float* r1  = x1b + a*DDW*4;
    const float* r2  = x2b + a*DDW*4;
    float4 X[4], Y[4], I[4];
    #pragma unroll
    for (int k = 0; k < 4; k++){
      float4 sv = ld4z(row, t0 + 2*k);
      X[k] = ld4z(r1, t0 + 2*k);
      Y[k] = ld4z(r2, t0 + 2*k);
      I[k] = f4add(f4add(sv, X[k]), Y[k]);
    }
    float acc[16];
    #pragma unroll
    for (int o = 0; o < 16; o++) acc[o] = 0.f;
    #pragma unroll
    for (int j = 0; j < 2; j++){
      float t[4];
      #pragma unroll
      for (int o = 0; o < 4; o++){
        float y = dot4(sh_w3[o], I[j]) + dot4(sh_w3[4+o], I[j+1]) + dot4(sh_w3[8+o], I[j+2]);
        t[o] = (y - m3)*i3;
      }
      float4 tv = make_float4(t[0], t[1], t[2], t[3]);
      float4 x3 = make_float4(geluf(dot4(sh_p3[0], tv)), geluf(dot4(sh_p3[1], tv)),
                              geluf(dot4(sh_p3[2], tv)), geluf(dot4(sh_p3[3], tv)));
      float4 u1 = X[j+1], u2 = Y[j+1];
      // cat stats (unnormalized x1,x2,x3 at this output position)
      sum += u1.x+u1.y+u1.z+u1.w + u2.x+u2.y+u2.z+u2.w + x3.x+x3.y+x3.z+x3.w;
      sq = fmaf(u1.x,u1.x, fmaf(u1.y,u1.y, fmaf(u1.z,u1.z, fmaf(u1.w,u1.w, sq))));
      sq = fmaf(u2.x,u2.x, fmaf(u2.y,u2.y, fmaf(u2.z,u2.z, fmaf(u2.w,u2.w, sq))));
      sq = fmaf(x3.x,x3.x, fmaf(x3.y,x3.y, fmaf(x3.z,x3.z, fmaf(x3.w,x3.w, sq))));
      // v[p] = cw · xcat (raw)
      float v[4];
      #pragma unroll
      for (int p = 0; p < 4; p++){
        const float* cwp = sh_cw + p*12;
        float a2 = cwp[0]*u1.x + cwp[1]*u1.y + cwp[2]*u1.z + cwp[3]*u1.w;
        a2 = fmaf(cwp[4], u2.x, fmaf(cwp[5], u2.y, fmaf(cwp[6], u2.z, fmaf(cwp[7], u2.w, a2))));
        a2 = fmaf(cwp[8], x3.x, fmaf(cwp[9], x3.y, fmaf(cwp[10], x3.z, fmaf(cwp[11], x3.w, a2))));
        v[p] = a2;
      }
      const float* cb = sh_c2 + (t0 + 2 + 2*j);
      #pragma unroll
      for (int o = 0; o < 16; o++){
        const float* co = cb + o*256;
        acc[o] = fmaf(v[0], co[0], fmaf(v[1], co[64], fmaf(v[2], co[128], fmaf(v[3], co[192], acc[o]))));
      }
    }
    // reduce zraw over the row (warp) and store
    #pragma unroll
    for (int o = 0; o < 16; o++){
      #pragma unroll
      for (int off2 = 16; off2; off2 >>= 1)
        acc[o] += __shfl_xor_sync(0xffffffffu, acc[o], off2);
    }
    if (lane == 0){
      int ag = chk*ROWS + a;
      float4* dst = reinterpret_cast<float4*>(g_z + ((size_t)b*AA + ag)*16);
      dst[0] = make_float4(acc[0],  acc[1],  acc[2],  acc[3]);
      dst[1] = make_float4(acc[4],  acc[5],  acc[6],  acc[7]);
      dst[2] = make_float4(acc[8],  acc[9],  acc[10], acc[11]);
      dst[3] = make_float4(acc[12], acc[13], acc[14], acc[15]);
    }
  }
  blockReduceStore(sum, sq, &g_p4[blockIdx.x]);
}

// ============ K4: affine-correct zraw -> LN -> +w -> 1x1(17->1) -> LN -> out ============
__global__ void __launch_bounds__(NTH)
k_final(const float* __restrict__ w, const float* __restrict__ cw,
        const float* __restrict__ c2w, const float* __restrict__ c3w,
        float* __restrict__ out)
{
  __shared__ float sh_z[AA*17];
  __shared__ float sh_red[18];
  __shared__ float sh_c3[17];
  __shared__ float sh_K[16];
  const int b = blockIdx.x, tid = threadIdx.x;
  if (tid < 17) sh_c3[tid] = c3w[tid];
  if (tid < 16){
    float csum[4];
    #pragma unroll
    for (int p = 0; p < 4; p++){
      float t = 0.f;
      #pragma unroll
      for (int c = 0; c < 12; c++) t += cw[p*12 + c];
      csum[p] = t;
    }
    float kk = 0.f;
    #pragma unroll
    for (int p = 0; p < 4; p++){
      const float* cb = c2w + tid*256 + p*64;
      float t = 0.f;
      for (int d = 0; d < 64; d++) t += cb[d];
      kk = fmaf(csum[p], t, kk);
    }
    sh_K[tid] = kk;
  }
  float mc, icat; finalizeStats(g_p4, b, INV_N12, mc, icat);
  __syncthreads();

  const float4* zsrc = reinterpret_cast<const float4*>(g_z + (size_t)b*AA*16);
  float sz = 0.f, qz = 0.f;
  for (int idx = tid; idx < AA*4; idx += NTH){
    float4 v = zsrc[idx];
    int a = idx >> 2, o4 = (idx & 3)*4;
    v.x = icat*(v.x - mc*sh_K[o4+0]);
    v.y = icat*(v.y - mc*sh_K[o4+1]);
    v.z = icat*(v.z - mc*sh_K[o4+2]);
    v.w = icat*(v.w - mc*sh_K[o4+3]);
    float* dst = sh_z + a*17 + o4;
    dst[0] = v.x; dst[1] = v.y; dst[2] = v.z; dst[3] = v.w;
    sz += v.x+v.y+v.z+v.w;
    qz = fmaf(v.x,v.x, fmaf(v.y,v.y, fmaf(v.z,v.z, fmaf(v.w,v.w, qz))));
  }
  blockReduce2(sz, qz, sh_red);
  const float invN4 = 1.f/(16.f*(float)AA);
  float m4 = sz*invN4;
  float i4 = rsqrtf(fmaf(-m4, m4, qz*invN4) + EPSF);

  float rv[2]; float sr = 0.f, qr = 0.f;
  #pragma unroll
  for (int j = 0; j < 2; j++){
    int a = tid + j*NTH;
    float r = sh_c3[16]*w[(size_t)b*AA + a];
    const float* zr = sh_z + a*17;
    #pragma unroll
    for (int o = 0; o < 16; o++)
      r = fmaf(sh_c3[o], (zr[o] - m4)*i4, r);
    rv[j] = r; sr += r; qr = fmaf(r, r, qr);
  }
  blockReduce2(sr, qr, sh_red);
  float m5 = sr*(1.f/(float)AA);
  float i5 = rsqrtf(fmaf(-m5, m5, qr*(1.f/(float)AA)) + EPSF);
  #pragma unroll
  for (int j = 0; j < 2; j++)
    out[(size_t)b*AA + tid + j*NTH] = (rv[j] - m5)*i5;
}

extern "C" void kernel_launch(void* const* d_in, const int* in_sizes, int n_in,
                              void* d_out, int out_size)
{
  (void)in_sizes; (void)n_in; (void)out_size;
  const float* s    = (const float*)d_in[0];
  const float* w    = (const float*)d_in[1];
  const float* d1w1 = (const float*)d_in[2];
  const float* d1w2 = (const float*)d_in[3];
  const float* d2w1 = (const float*)d_in[4];
  const float* d2w2 = (const float*)d_in[5];
  const float* d3w1 = (const float*)d_in[6];
  const float* d3w2 = (const float*)d_in[7];
  const float* cw   = (const float*)d_in[8];
  const float* c2w  = (const float*)d_in[9];
  const float* c3w  = (const float*)d_in[10];
  float* out = (float*)d_out;

  k_statsA<<<BB*CH, NTH>>>(s, d1w1);
  k_passB <<<BB*CH, NTH>>>(s, d1w1, d1w2, d2w1);
  k_passC <<<BB*CH, NTH>>>(s, d2w1, d2w2, d3w1);
  k_passD <<<BB*CH, NTH>>>(s, d3w1, d3w2, cw, c2w);
  k_final <<<BB,    NTH>>>(w, cw, c2w, c3w, out);
}

// round 4
// speedup vs baseline: 1.6497x; 1.1860x over previous
#include <cuda_runtime.h>
#include <math.h>

#define BB    256
#define AA    512
#define DDW   64
#define NPOS  (AA*DDW)        // 32768 positions per sample
#define NTH   256
#define CH    8               // chunks per sample
#define ROWS  (AA/CH)         // 64 rows per chunk
#define EPSF  1e-5f

// Scratch: x1/x2 activations [b][a][d][c] (c fastest); zraw [b][a][o]
__device__ float  g_x1[(size_t)BB*NPOS*4];
__device__ float  g_x2[(size_t)BB*NPOS*4];
__device__ float  g_z [(size_t)BB*AA*16];
__device__ float2 g_p1[BB*CH], g_p2[BB*CH], g_p3[BB*CH], g_p4[BB*CH];

__device__ __forceinline__ float4 f4add(float4 a, float4 b){
  return make_float4(a.x+b.x, a.y+b.y, a.z+b.z, a.w+b.w);
}
__device__ __forceinline__ float dot4(float4 w, float4 v){
  return fmaf(w.x, v.x, fmaf(w.y, v.y, fmaf(w.z, v.z, w.w*v.w)));
}
__device__ __forceinline__ float4 ld4z(const float* rowBase, int d){
  if ((unsigned)d < (unsigned)DDW)
    return *reinterpret_cast<const float4*>(rowBase + d*4);
  return make_float4(0.f, 0.f, 0.f, 0.f);
}
__device__ __forceinline__ float geluf(float x){
  return 0.5f * x * (1.f + erff(x * 0.70710678118654752440f));
}
__device__ __forceinline__ void loadConvW(const float* __restrict__ wp, float4 wk[3][4]){
  #pragma unroll
  for (int o = 0; o < 4; o++)
    #pragma unroll
    for (int k = 0; k < 3; k++)
      wk[k][o] = make_float4(wp[o*12 + 0 + k], wp[o*12 + 3 + k],
                             wp[o*12 + 6 + k], wp[o*12 + 9 + k]);
}
__device__ __forceinline__ float4 shflup4(float4 v){
  float4 r;
  r.x = __shfl_up_sync(0xffffffffu, v.x, 1);
  r.y = __shfl_up_sync(0xffffffffu, v.y, 1);
  r.z = __shfl_up_sync(0xffffffffu, v.z, 1);
  r.w = __shfl_up_sync(0xffffffffu, v.w, 1);
  return r;
}
__device__ __forceinline__ float4 shfldn4(float4 v){
  float4 r;
  r.x = __shfl_down_sync(0xffffffffu, v.x, 1);
  r.y = __shfl_down_sync(0xffffffffu, v.y, 1);
  r.z = __shfl_down_sync(0xffffffffu, v.z, 1);
  r.w = __shfl_down_sync(0xffffffffu, v.w, 1);
  return r;
}

__device__ __forceinline__ void blockReduceStore(float s, float q, float2* dst){
  #pragma unroll
  for (int off = 16; off > 0; off >>= 1){
    s += __shfl_xor_sync(0xffffffffu, s, off);
    q += __shfl_xor_sync(0xffffffffu, q, off);
  }
  __shared__ float red[16];
  int wp = threadIdx.x >> 5, ln = threadIdx.x & 31;
  if (ln == 0){ red[wp] = s; red[8+wp] = q; }
  __syncthreads();
  if (threadIdx.x == 0){
    float ss = 0.f, qq = 0.f;
    #pragma unroll
    for (int i = 0; i < 8; i++){ ss += red[i]; qq += red[8+i]; }
    *dst = make_float2(ss, qq);
  }
}

__device__ __forceinline__ void finalizeStats(const float2* __restrict__ part, int b,
                                              float invN, float& m, float& inv){
  float s = 0.f, q = 0.f;
  #pragma unroll
  for (int i = 0; i < CH; i++){
    float2 p = __ldg(&part[b*CH + i]);
    s += p.x; q += p.y;
  }
  m = s*invN;
  inv = rsqrtf(fmaf(-m, m, q*invN) + EPSF);
}

__device__ __forceinline__ void blockReduce2(float& s, float& q, volatile float* red){
  #pragma unroll
  for (int off = 16; off > 0; off >>= 1){
    s += __shfl_xor_sync(0xffffffffu, s, off);
    q += __shfl_xor_sync(0xffffffffu, q, off);
  }
  int wp = threadIdx.x >> 5, ln = threadIdx.x & 31;
  __syncthreads();
  if (ln == 0){ red[wp] = s; red[8+wp] = q; }
  __syncthreads();
  if (threadIdx.x == 0){
    float ss = 0.f, qq = 0.f;
    #pragma unroll
    for (int i = 0; i < 8; i++){ ss += red[i]; qq += red[8+i]; }
    red[16] = ss; red[17] = qq;
  }
  __syncthreads();
  s = red[16]; q = red[17];
}

#define INV_N1  (1.f/(4.f*(float)NPOS))
#define INV_N12 (1.f/(12.f*(float)NPOS))

// ============ K0: stats of y1 = conv1(s) ============
__global__ void __launch_bounds__(NTH, 2)
k_statsA(const float* __restrict__ s, const float* __restrict__ d1w1)
{
  const int b = blockIdx.x >> 3, chk = blockIdx.x & 7;
  const int lane = threadIdx.x & 31, warp = threadIdx.x >> 5;
  const int i = lane & 15, e = lane >> 4;
  const int t0 = 4*i + e - 2;                  // leftmost tap
  const float* sb = s + (size_t)b*NPOS*4 + (size_t)chk*ROWS*DDW*4;
  float4 wk[3][4]; loadConvW(d1w1, wk);
  float sum = 0.f, sq = 0.f;
  for (int r = 0; r < 8; ++r){
    int a = warp + 8*r;
    const float* row = sb + a*DDW*4;
    float4 S[4];
    #pragma unroll
    for (int k = 0; k < 4; k++) S[k] = ld4z(row, t0 + 2*k);
    #pragma unroll
    for (int j = 0; j < 2; j++){
      #pragma unroll
      for (int o = 0; o < 4; o++){
        float y = dot4(wk[0][o], S[j]) + dot4(wk[1][o], S[j+1]) + dot4(wk[2][o], S[j+2]);
        sum += y; sq = fmaf(y, y, sq);
      }
    }
  }
  blockReduceStore(sum, sq, &g_p1[blockIdx.x]);
}

// ============ K1: x1 = gelu(pw1(LN(y1))); write x1; stats of y2 = conv2(s+x1) ============
__global__ void __launch_bounds__(NTH, 2)
k_passB(const float* __restrict__ s, const float* __restrict__ d1w1,
        const float* __restrict__ d1w2, const float* __restrict__ d2w1)
{
  __shared__ float4 sh_w2[12];   // stats conv weights [k*4+o]
  __shared__ float4 sh_p1[4];    // pointwise weights
  const int b = blockIdx.x >> 3, chk = blockIdx.x & 7, tid = threadIdx.x;
  const int lane = tid & 31, warp = tid >> 5;
  const int i = lane & 15, e = lane >> 4;
  const int t0 = 4*i + e - 2;
  const size_t off = (size_t)b*NPOS*4 + (size_t)chk*ROWS*DDW*4;
  const float* sb  = s + off;
  float*       x1b = g_x1 + off;
  if (tid < 12){
    int k = tid >> 2, o = tid & 3;
    sh_w2[tid] = make_float4(d2w1[o*12+k], d2w1[o*12+3+k], d2w1[o*12+6+k], d2w1[o*12+9+k]);
  }
  if (tid < 4) sh_p1[tid] = make_float4(d1w2[tid*4+0], d1w2[tid*4+1], d1w2[tid*4+2], d1w2[tid*4+3]);
  float4 w1k[3][4]; loadConvW(d1w1, w1k);
  float m1, i1; finalizeStats(g_p1, b, INV_N1, m1, i1);
  __syncthreads();

  float sum = 0.f, sq = 0.f;
  for (int r = 0; r < 8; ++r){
    int a = warp + 8*r;
    const float* row = sb + a*DDW*4;
    float4 S[4];
    #pragma unroll
    for (int k = 0; k < 4; k++) S[k] = ld4z(row, t0 + 2*k);
    float4 xv[2];
    #pragma unroll
    for (int j = 0; j < 2; j++){
      float t[4];
      #pragma unroll
      for (int o = 0; o < 4; o++){
        float y = dot4(w1k[0][o], S[j]) + dot4(w1k[1][o], S[j+1]) + dot4(w1k[2][o], S[j+2]);
        t[o] = (y - m1)*i1;
      }
      float4 tv = make_float4(t[0], t[1], t[2], t[3]);
      xv[j] = make_float4(geluf(dot4(sh_p1[0], tv)), geluf(dot4(sh_p1[1], tv)),
                          geluf(dot4(sh_p1[2], tv)), geluf(dot4(sh_p1[3], tv)));
      reinterpret_cast<float4*>(x1b)[a*DDW + t0 + 2 + 2*j] = xv[j];
    }
    float4 z4 = make_float4(0.f,0.f,0.f,0.f);
    float4 xn0 = shflup4(xv[1]); if (i == 0)  xn0 = z4;
    float4 xn3 = shfldn4(xv[0]); if (i == 15) xn3 = z4;
    float4 XN[4] = {xn0, xv[0], xv[1], xn3};
    #pragma unroll
    for (int j = 0; j < 2; j++){
      float4 U0 = f4add(S[j],   XN[j]);
      float4 U1 = f4add(S[j+1], XN[j+1]);
      float4 U2 = f4add(S[j+2], XN[j+2]);
      #pragma unroll
      for (int o = 0; o < 4; o++){
        float y = dot4(sh_w2[o], U0) + dot4(sh_w2[4+o], U1) + dot4(sh_w2[8+o], U2);
        sum += y; sq = fmaf(y, y, sq);
      }
    }
  }
  blockReduceStore(sum, sq, &g_p2[blockIdx.x]);
}

// ============ K2: x2; write x2; stats of y3 = conv3(s+x1+x2) ============
__global__ void __launch_bounds__(NTH, 2)
k_passC(const float* __restrict__ s, const float* __restrict__ d2w1,
        const float* __restrict__ d2w2, const float* __restrict__ d3w1)
{
  __shared__ float4 sh_w3[12];
  __shared__ float4 sh_p2[4];
  const int b = blockIdx.x >> 3, chk = blockIdx.x & 7, tid = threadIdx.x;
  const int lane = tid & 31, warp = tid >> 5;
  const int i = lane & 15, e = lane >> 4;
  const int t0 = 4*i + e - 2;
  const size_t off = (size_t)b*NPOS*4 + (size_t)chk*ROWS*DDW*4;
  const float* sb  = s + off;
  const float* x1b = g_x1 + off;
  float*       x2b = g_x2 + off;
  if (tid < 12){
    int k = tid >> 2, o = tid & 3;
    sh_w3[tid] = make_float4(d3w1[o*12+k], d3w1[o*12+3+k], d3w1[o*12+6+k], d3w1[o*12+9+k]);
  }
  if (tid < 4) sh_p2[tid] = make_float4(d2w2[tid*4+0], d2w2[tid*4+1], d2w2[tid*4+2], d2w2[tid*4+3]);
  float4 w2k[3][4]; loadConvW(d2w1, w2k);
  float m2, i2; finalizeStats(g_p2, b, INV_N1, m2, i2);
  __syncthreads();

  float sum = 0.f, sq = 0.f;
  for (int r = 0; r < 8; ++r){
    int a = warp + 8*r;
    const float* row = sb  + a*DDW*4;
    const float* r1  = x1b + a*DDW*4;
    float4 I[4];
    #pragma unroll
    for (int k = 0; k < 4; k++)
      I[k] = f4add(ld4z(row, t0 + 2*k), ld4z(r1, t0 + 2*k));
    float4 xv[2];
    #pragma unroll
    for (int j = 0; j < 2; j++){
      float t[4];
      #pragma unroll
      for (int o = 0; o < 4; o++){
        float y = dot4(w2k[0][o], I[j]) + dot4(w2k[1][o], I[j+1]) + dot4(w2k[2][o], I[j+2]);
        t[o] = (y - m2)*i2;
      }
      float4 tv = make_float4(t[0], t[1], t[2], t[3]);
      xv[j] = make_float4(geluf(dot4(sh_p2[0], tv)), geluf(dot4(sh_p2[1], tv)),
                          geluf(dot4(sh_p2[2], tv)), geluf(dot4(sh_p2[3], tv)));
      reinterpret_cast<float4*>(x2b)[a*DDW + t0 + 2 + 2*j] = xv[j];
    }
    float4 z4 = make_float4(0.f,0.f,0.f,0.f);
    float4 xn0 = shflup4(xv[1]); if (i == 0)  xn0 = z4;
    float4 xn3 = shfldn4(xv[0]); if (i == 15) xn3 = z4;
    float4 XN[4] = {xn0, xv[0], xv[1], xn3};
    #pragma unroll
    for (int j = 0; j < 2; j++){
      float4 U0 = f4add(I[j],   XN[j]);
      float4 U1 = f4add(I[j+1], XN[j+1]);
      float4 U2 = f4add(I[j+2], XN[j+2]);
      #pragma unroll
      for (int o = 0; o < 4; o++){
        float y = dot4(sh_w3[o], U0) + dot4(sh_w3[4+o], U1) + dot4(sh_w3[8+o], U2);
        sum += y; sq = fmaf(y, y, sq);
      }
    }
  }
  blockReduceStore(sum, sq, &g_p3[blockIdx.x]);
}

// ============ K3: x3 (regs) + zraw (phase-split, parity-packed c2w) + cat stats ============
__global__ void __launch_bounds__(NTH, 2)
k_passD(const float* __restrict__ s, const float* __restrict__ d3w1,
        const float* __restrict__ d3w2, const float* __restrict__ cw,
        const float* __restrict__ c2w)
{
  __shared__ float  sh_c2[16*4*2*32];  // [o][p][par][m], m = d>>1
  __shared__ float  sh_cw[48];         // [p*12+c]
  __shared__ float4 sh_w3[12];
  __shared__ float4 sh_p3[4];
  const int b = blockIdx.x >> 3, chk = blockIdx.x & 7, tid = threadIdx.x;
  const int lane = tid & 31, warp = tid >> 5;
  const int i = lane & 15, e = lane >> 4;
  const int t0 = 4*i + e - 2;
  const int par = e, mbase = 2*i;      // thread's two outputs: m = 2i, 2i+1
  const size_t off = (size_t)b*NPOS*4 + (size_t)chk*ROWS*DDW*4;
  const float* sb  = s + off;
  const float* x1b = g_x1 + off;
  const float* x2b = g_x2 + off;
  // c2w global layout [o*256 + p*64 + d] -> parity layout
  for (int k = tid; k < 4096; k += NTH){
    int m = k & 31, pr = (k >> 5) & 1, p = (k >> 6) & 3, o = k >> 8;
    sh_c2[k] = c2w[o*256 + p*64 + 2*m + pr];
  }
  if (tid < 48) sh_cw[tid] = cw[tid];
  if (tid < 12){
    int k = tid >> 2, o = tid & 3;
    sh_w3[tid] = make_float4(d3w1[o*12+k], d3w1[o*12+3+k], d3w1[o*12+6+k], d3w1[o*12+9+k]);
  }
  if (tid < 4) sh_p3[tid] = make_float4(d3w2[tid*4+0], d3w2[tid*4+1], d3w2[tid*4+2], d3w2[tid*4+3]);
  float m3, i3; finalizeStats(g_p3, b, INV_N1, m3, i3);
  __syncthreads();

  float sum = 0.f, sq = 0.f;
  for (int g = 0; g < 2; ++g){
    float V[4][2][4];                  // [row][j][p]
    // -------- phase 1: 4 rows -> v[p] in registers --------
    #pragma unroll
    for (int r = 0; r < 4; ++r){
      int a = warp + 8*(4*g + r);
      const float* row = sb  + a*DDW*4;
      const float* r1  = x1b + a*DDW*4;
      const float* r2  = x2b + a*DDW*4;
      float4 X[4], Y[4], I[4];
      #pragma unroll
      for (int k = 0; k < 4; k++){
        float4 sv = ld4z(row, t0 + 2*k);
        X[k] = ld4z(r1, t0 + 2*k);
        Y[k] = ld4z(r2, t0 + 2*k);
        I[k] = f4add(f4add(sv, X[k]), Y[k]);
      }
      #pragma unroll
      for (int j = 0; j < 2; j++){
        float t[4];
        #pragma unroll
        for (int o = 0; o < 4; o++){
          float y = dot4(sh_w3[o], I[j]) + dot4(sh_w3[4+o], I[j+1]) + dot4(sh_w3[8+o], I[j+2]);
          t[o] = (y - m3)*i3;
        }
        float4 tv = make_float4(t[0], t[1], t[2], t[3]);
        float4 x3 = make_float4(geluf(dot4(sh_p3[0], tv)), geluf(dot4(sh_p3[1], tv)),
                                geluf(dot4(sh_p3[2], tv)), geluf(dot4(sh_p3[3], tv)));
        float4 u1 = X[j+1], u2 = Y[j+1];
        sum += u1.x+u1.y+u1.z+u1.w + u2.x+u2.y+u2.z+u2.w + x3.x+x3.y+x3.z+x3.w;
        sq = fmaf(u1.x,u1.x, fmaf(u1.y,u1.y, fmaf(u1.z,u1.z, fmaf(u1.w,u1.w, sq))));
        sq = fmaf(u2.x,u2.x, fmaf(u2.y,u2.y, fmaf(u2.z,u2.z, fmaf(u2.w,u2.w, sq))));
        sq = fmaf(x3.x,x3.x, fmaf(x3.y,x3.y, fmaf(x3.z,x3.z, fmaf(x3.w,x3.w, sq))));
        #pragma unroll
        for (int p = 0; p < 4; p++){
          const float* cwp = sh_cw + p*12;
          float a2 = cwp[0]*u1.x + cwp[1]*u1.y + cwp[2]*u1.z + cwp[3]*u1.w;
          a2 = fmaf(cwp[4], u2.x, fmaf(cwp[5], u2.y, fmaf(cwp[6], u2.z, fmaf(cwp[7], u2.w, a2))));
          a2 = fmaf(cwp[8], x3.x, fmaf(cwp[9], x3.y, fmaf(cwp[10], x3.z, fmaf(cwp[11], x3.w, a2))));
          V[r][j][p] = a2;
        }
      }
    }
    // -------- phase 2: z[o] for the 4 rows; c2w read once per o --------
    #pragma unroll
    for (int o = 0; o < 16; ++o){
      float2 wv[4];
      #pragma unroll
      for (int p = 0; p < 4; p++)
        wv[p] = *reinterpret_cast<const float2*>(
                  &sh_c2[((o*4 + p)*2 + par)*32 + mbase]);
      float acc[4];
      #pragma unroll
      for (int r = 0; r < 4; ++r){
        float a0 = 0.f;
        #pragma unroll
        for (int p = 0; p < 4; p++)
          a0 = fmaf(wv[p].x, V[r][0][p], fmaf(wv[p].y, V[r][1][p], a0));
        acc[r] = a0;
      }
      // split-butterfly: 4 values over 32 lanes in 6 shuffles
      const bool b4 = (lane & 16) != 0, b3 = (lane & 8) != 0;
      float s0 = b4 ? acc[2] : acc[0];
      float s1 = b4 ? acc[3] : acc[1];
      s0 += __shfl_xor_sync(0xffffffffu, b4 ? acc[0] : acc[2], 16);
      s1 += __shfl_xor_sync(0xffffffffu, b4 ? acc[1] : acc[3], 16);
      float sv = b3 ? s1 : s0;
      sv += __shfl_xor_sync(0xffffffffu, b3 ? s0 : s1, 8);
      sv += __shfl_xor_sync(0xffffffffu, sv, 4);
      sv += __shfl_xor_sync(0xffffffffu, sv, 2);
      sv += __shfl_xor_sync(0xffffffffu, sv, 1);
      if ((lane & 7) == 0){
        int r = ((lane >> 4) << 1) | ((lane >> 3) & 1);
        int ag = chk*ROWS + warp + 8*(4*g + r);
        g_z[((size_t)b*AA + ag)*16 + o] = sv;
      }
    }
  }
  blockReduceStore(sum, sq, &g_p4[blockIdx.x]);
}

// ============ K4: affine-correct zraw -> LN -> +w -> 1x1(17->1) -> LN -> out ============
__global__ void __launch_bounds__(NTH)
k_final(const float* __restrict__ w, const float* __restrict__ cw,
        const float* __restrict__ c2w, const float* __restrict__ c3w,
        float* __restrict__ out)
{
  __shared__ float sh_z[AA*17];
  __shared__ float sh_red[18];
  __shared__ float sh_c3[17];
  __shared__ float sh_K[16];
  const int b = blockIdx.x, tid = threadIdx.x;
  if (tid < 17) sh_c3[tid] = c3w[tid];
  if (tid < 16){
    float csum[4];
    #pragma unroll
    for (int p = 0; p < 4; p++){
      float t = 0.f;
      #pragma unroll
      for (int c = 0; c < 12; c++) t += cw[p*12 + c];
      csum[p] = t;
    }
    float kk = 0.f;
    #pragma unroll
    for (int p = 0; p < 4; p++){
      const float* cb = c2w + tid*256 + p*64;
      float t = 0.f;
      for (int d = 0; d < 64; d++) t += cb[d];
      kk = fmaf(csum[p], t, kk);
    }
    sh_K[tid] = kk;
  }
  float mc, icat; finalizeStats(g_p4, b, INV_N12, mc, icat);
  __syncthreads();

  const float4* zsrc = reinterpret_cast<const float4*>(g_z + (size_t)b*AA*16);
  float sz = 0.f, qz = 0.f;
  for (int idx = tid; idx < AA*4; idx += NTH){
    float4 v = zsrc[idx];
    int a = idx >> 2, o4 = (idx & 3)*4;
    v.x = icat*(v.x - mc*sh_K[o4+0]);
    v.y = icat*(v.y - mc*sh_K[o4+1]);
    v.z = icat*(v.z - mc*sh_K[o4+2]);
    v.w = icat*(v.w - mc*sh_K[o4+3]);
    float* dst = sh_z + a*17 + o4;
    dst[0] = v.x; dst[1] = v.y; dst[2] = v.z; dst[3] = v.w;
    sz += v.x+v.y+v.z+v.w;
    qz = fmaf(v.x,v.x, fmaf(v.y,v.y, fmaf(v.z,v.z, fmaf(v.w,v.w, qz))));
  }
  blockReduce2(sz, qz, sh_red);
  const float invN4 = 1.f/(16.f*(float)AA);
  float m4 = sz*invN4;
  float i4 = rsqrtf(fmaf(-m4, m4, qz*invN4) + EPSF);

  float rv[2]; float sr = 0.f, qr = 0.f;
  #pragma unroll
  for (int j = 0; j < 2; j++){
    int a = tid + j*NTH;
    float r = sh_c3[16]*w[(size_t)b*AA + a];
    const float* zr = sh_z + a*17;
    #pragma unroll
    for (int o = 0; o < 16; o++)
      r = fmaf(sh_c3[o], (zr[o] - m4)*i4, r);
    rv[j] = r; sr += r; qr = fmaf(r, r, qr);
  }
  blockReduce2(sr, qr, sh_red);
  float m5 = sr*(1.f/(float)AA);
  float i5 = rsqrtf(fmaf(-m5, m5, qr*(1.f/(float)AA)) + EPSF);
  #pragma unroll
  for (int j = 0; j < 2; j++)
    out[(size_t)b*AA + tid + j*NTH] = (rv[j] - m5)*i5;
}

extern "C" void kernel_launch(void* const* d_in, const int* in_sizes, int n_in,
                              void* d_out, int out_size)
{
  (void)in_sizes; (void)n_in; (void)out_size;
  const float* s    = (const float*)d_in[0];
  const float* w    = (const float*)d_in[1];
  const float* d1w1 = (const float*)d_in[2];
  const float* d1w2 = (const float*)d_in[3];
  const float* d2w1 = (const float*)d_in[4];
  const float* d2w2 = (const float*)d_in[5];
  const float* d3w1 = (const float*)d_in[6];
  const float* d3w2 = (const float*)d_in[7];
  const float* cw   = (const float*)d_in[8];
  const float* c2w  = (const float*)d_in[9];
  const float* c3w  = (const float*)d_in[10];
  float* out = (float*)d_out;

  k_statsA<<<BB*CH, NTH>>>(s, d1w1);
  k_passB <<<BB*CH, NTH>>>(s, d1w1, d1w2, d2w1);
  k_passC <<<BB*CH, NTH>>>(s, d2w1, d2w2, d3w1);
  k_passD <<<BB*CH, NTH>>>(s, d3w1, d3w2, cw, c2w);
  k_final <<<BB,    NTH>>>(w, cw, c2w, c3w, out);
}

// round 5
// speedup vs baseline: 2.0543x; 1.2453x over previous
#include <cuda_runtime.h>
#include <math.h>

#define BB    256
#define AA    512
#define DDW   64
#define NPOS  (AA*DDW)        // 32768 positions per sample
#define NTH   256
#define CH    8               // chunks per sample
#define ROWS  (AA/CH)         // 64 rows per chunk
#define EPSF  1e-5f
#define FULLM 0xffffffffu

// Scratch: x1/x2 activations [b][a][d][c] (c fastest); zraw [b][a][o]
__device__ float  g_x1[(size_t)BB*NPOS*4];
__device__ float  g_x2[(size_t)BB*NPOS*4];
__device__ float  g_z [(size_t)BB*AA*16];
__device__ float2 g_p1[BB*CH], g_p2[BB*CH], g_p3[BB*CH], g_p4[BB*CH];

__device__ __forceinline__ float4 f4add(float4 a, float4 b){
  return make_float4(a.x+b.x, a.y+b.y, a.z+b.z, a.w+b.w);
}
__device__ __forceinline__ float dot4(float4 w, float4 v){
  return fmaf(w.x, v.x, fmaf(w.y, v.y, fmaf(w.z, v.z, w.w*v.w)));
}
__device__ __forceinline__ float geluf(float x){
  return 0.5f * x * (1.f + erff(x * 0.70710678118654752440f));
}
__device__ __forceinline__ void loadConvW(const float* __restrict__ wp, float4 wk[3][4]){
  #pragma unroll
  for (int o = 0; o < 4; o++)
    #pragma unroll
    for (int k = 0; k < 3; k++)
      wk[k][o] = make_float4(wp[o*12 + 0 + k], wp[o*12 + 3 + k],
                             wp[o*12 + 6 + k], wp[o*12 + 9 + k]);
}
__device__ __forceinline__ float4 shflup2_4(float4 v){
  float4 r;
  r.x = __shfl_up_sync(FULLM, v.x, 2);
  r.y = __shfl_up_sync(FULLM, v.y, 2);
  r.z = __shfl_up_sync(FULLM, v.z, 2);
  r.w = __shfl_up_sync(FULLM, v.w, 2);
  return r;
}
__device__ __forceinline__ float4 shfldn2_4(float4 v){
  float4 r;
  r.x = __shfl_down_sync(FULLM, v.x, 2);
  r.y = __shfl_down_sync(FULLM, v.y, 2);
  r.z = __shfl_down_sync(FULLM, v.z, 2);
  r.w = __shfl_down_sync(FULLM, v.w, 2);
  return r;
}
__device__ __forceinline__ float4 shflsel4(float4 v, int sl){
  float4 r;
  r.x = __shfl_sync(FULLM, v.x, sl);
  r.y = __shfl_sync(FULLM, v.y, sl);
  r.z = __shfl_sync(FULLM, v.z, sl);
  r.w = __shfl_sync(FULLM, v.w, sl);
  return r;
}
// Build the 6 dilated taps for outputs d=lane and d=lane+32 from T0=v(lane), T1=v(lane+32).
struct Taps { float4 m0, p0, m1, p1; };
__device__ __forceinline__ Taps makeTaps(float4 T0, float4 T1, int lane){
  const float4 z4 = make_float4(0.f,0.f,0.f,0.f);
  Taps t;
  t.m0 = shflup2_4(T0);                 if (lane < 2)  t.m0 = z4;   // v(lane-2)
  t.p0 = shflsel4((lane < 2) ? T1 : T0, (lane+2)  & 31);            // v(lane+2)
  t.m1 = shflsel4((lane >= 30) ? T0 : T1, (lane-2) & 31);           // v(lane+30)
  t.p1 = shfldn2_4(T1);                 if (lane >= 30) t.p1 = z4;  // v(lane+34)
  return t;
}

__device__ __forceinline__ void blockReduceStore(float s, float q, float2* dst){
  #pragma unroll
  for (int off = 16; off > 0; off >>= 1){
    s += __shfl_xor_sync(FULLM, s, off);
    q += __shfl_xor_sync(FULLM, q, off);
  }
  __shared__ float red[16];
  int wp = threadIdx.x >> 5, ln = threadIdx.x & 31;
  if (ln == 0){ red[wp] = s; red[8+wp] = q; }
  __syncthreads();
  if (threadIdx.x == 0){
    float ss = 0.f, qq = 0.f;
    #pragma unroll
    for (int i = 0; i < 8; i++){ ss += red[i]; qq += red[8+i]; }
    *dst = make_float2(ss, qq);
  }
}

__device__ __forceinline__ void finalizeStats(const float2* __restrict__ part, int b,
                                              float invN, float& m, float& inv){
  float s = 0.f, q = 0.f;
  #pragma unroll
  for (int i = 0; i < CH; i++){
    float2 p = __ldg(&part[b*CH + i]);
    s += p.x; q += p.y;
  }
  m = s*invN;
  inv = rsqrtf(fmaf(-m, m, q*invN) + EPSF);
}

__device__ __forceinline__ void blockReduce2(float& s, float& q, volatile float* red){
  #pragma unroll
  for (int off = 16; off > 0; off >>= 1){
    s += __shfl_xor_sync(FULLM, s, off);
    q += __shfl_xor_sync(FULLM, q, off);
  }
  int wp = threadIdx.x >> 5, ln = threadIdx.x & 31;
  __syncthreads();
  if (ln == 0){ red[wp] = s; red[8+wp] = q; }
  __syncthreads();
  if (threadIdx.x == 0){
    float ss = 0.f, qq = 0.f;
    #pragma unroll
    for (int i = 0; i < 8; i++){ ss += red[i]; qq += red[8+i]; }
    red[16] = ss; red[17] = qq;
  }
  __syncthreads();
  s = red[16]; q = red[17];
}

#define INV_N1  (1.f/(4.f*(float)NPOS))
#define INV_N12 (1.f/(12.f*(float)NPOS))

// ============ K0: stats of y1 = conv1(s) ============
__global__ void __launch_bounds__(NTH, 3)
k_statsA(const float* __restrict__ s, const float* __restrict__ d1w1)
{
  const int b = blockIdx.x >> 3, chk = blockIdx.x & 7;
  const int lane = threadIdx.x & 31, warp = threadIdx.x >> 5;
  const float4* sb = reinterpret_cast<const float4*>(
      s + (size_t)b*NPOS*4 + (size_t)chk*ROWS*DDW*4);
  float4 wk[3][4]; loadConvW(d1w1, wk);
  float sum = 0.f, sq = 0.f;
  for (int r = 0; r < 8; ++r){
    int a = warp + 8*r;
    float4 T0 = sb[a*DDW + lane], T1 = sb[a*DDW + lane + 32];
    Taps tp = makeTaps(T0, T1, lane);
    #pragma unroll
    for (int o = 0; o < 4; o++){
      float y0 = dot4(wk[0][o], tp.m0) + dot4(wk[1][o], T0) + dot4(wk[2][o], tp.p0);
      float y1 = dot4(wk[0][o], tp.m1) + dot4(wk[1][o], T1) + dot4(wk[2][o], tp.p1);
      sum += y0 + y1; sq = fmaf(y0, y0, fmaf(y1, y1, sq));
    }
  }
  blockReduceStore(sum, sq, &g_p1[blockIdx.x]);
}

// ============ K1: x1 = gelu(pw1(LN(y1))); write x1; stats of y2 = conv2(s+x1) ============
__global__ void __launch_bounds__(NTH, 3)
k_passB(const float* __restrict__ s, const float* __restrict__ d1w1,
        const float* __restrict__ d1w2, const float* __restrict__ d2w1)
{
  __shared__ float4 sh_w2[12];   // stats conv weights [k*4+o]
  __shared__ float4 sh_p1[4];    // pointwise weights
  const int b = blockIdx.x >> 3, chk = blockIdx.x & 7, tid = threadIdx.x;
  const int lane = tid & 31, warp = tid >> 5;
  const size_t off = (size_t)b*NPOS*4 + (size_t)chk*ROWS*DDW*4;
  const float4* sb  = reinterpret_cast<const float4*>(s + off);
  float4*       x1b = reinterpret_cast<float4*>(g_x1 + off);
  if (tid < 12){
    int k = tid >> 2, o = tid & 3;
    sh_w2[tid] = make_float4(d2w1[o*12+k], d2w1[o*12+3+k], d2w1[o*12+6+k], d2w1[o*12+9+k]);
  }
  if (tid < 4) sh_p1[tid] = make_float4(d1w2[tid*4+0], d1w2[tid*4+1], d1w2[tid*4+2], d1w2[tid*4+3]);
  float4 w1k[3][4]; loadConvW(d1w1, w1k);
  float m1, i1; finalizeStats(g_p1, b, INV_N1, m1, i1);
  __syncthreads();

  float sum = 0.f, sq = 0.f;
  for (int r = 0; r < 8; ++r){
    int a = warp + 8*r;
    float4 T0 = sb[a*DDW + lane], T1 = sb[a*DDW + lane + 32];
    Taps st = makeTaps(T0, T1, lane);
    float t0[4], t1[4];
    #pragma unroll
    for (int o = 0; o < 4; o++){
      float y0 = dot4(w1k[0][o], st.m0) + dot4(w1k[1][o], T0) + dot4(w1k[2][o], st.p0);
      float y1 = dot4(w1k[0][o], st.m1) + dot4(w1k[1][o], T1) + dot4(w1k[2][o], st.p1);
      t0[o] = (y0 - m1)*i1;  t1[o] = (y1 - m1)*i1;
    }
    float4 tv0 = make_float4(t0[0], t0[1], t0[2], t0[3]);
    float4 tv1 = make_float4(t1[0], t1[1], t1[2], t1[3]);
    float4 xv0 = make_float4(geluf(dot4(sh_p1[0], tv0)), geluf(dot4(sh_p1[1], tv0)),
                             geluf(dot4(sh_p1[2], tv0)), geluf(dot4(sh_p1[3], tv0)));
    float4 xv1 = make_float4(geluf(dot4(sh_p1[0], tv1)), geluf(dot4(sh_p1[1], tv1)),
                             geluf(dot4(sh_p1[2], tv1)), geluf(dot4(sh_p1[3], tv1)));
    x1b[a*DDW + lane]      = xv0;
    x1b[a*DDW + lane + 32] = xv1;
    // conv2 input = s + x1; taps of sum = s-taps + x-taps
    Taps xt = makeTaps(xv0, xv1, lane);
    float4 U0m = f4add(st.m0, xt.m0), U0c = f4add(T0, xv0), U0p = f4add(st.p0, xt.p0);
    float4 U1m = f4add(st.m1, xt.m1), U1c = f4add(T1, xv1), U1p = f4add(st.p1, xt.p1);
    #pragma unroll
    for (int o = 0; o < 4; o++){
      float y0 = dot4(sh_w2[o], U0m) + dot4(sh_w2[4+o], U0c) + dot4(sh_w2[8+o], U0p);
      float y1 = dot4(sh_w2[o], U1m) + dot4(sh_w2[4+o], U1c) + dot4(sh_w2[8+o], U1p);
      sum += y0 + y1; sq = fmaf(y0, y0, fmaf(y1, y1, sq));
    }
  }
  blockReduceStore(sum, sq, &g_p2[blockIdx.x]);
}

// ============ K2: x2; write x2; stats of y3 = conv3(s+x1+x2) ============
__global__ void __launch_bounds__(NTH, 3)
k_passC(const float* __restrict__ s, const float* __restrict__ d2w1,
        const float* __restrict__ d2w2, const float* __restrict__ d3w1)
{
  __shared__ float4 sh_w3[12];
  __shared__ float4 sh_p2[4];
  const int b = blockIdx.x >> 3, chk = blockIdx.x & 7, tid = threadIdx.x;
  const int lane = tid & 31, warp = tid >> 5;
  const size_t off = (size_t)b*NPOS*4 + (size_t)chk*ROWS*DDW*4;
  const float4* sb  = reinterpret_cast<const float4*>(s + off);
  const float4* x1b = reinterpret_cast<const float4*>(g_x1 + off);
  float4*       x2b = reinterpret_cast<float4*>(g_x2 + off);
  if (tid < 12){
    int k = tid >> 2, o = tid & 3;
    sh_w3[tid] = make_float4(d3w1[o*12+k], d3w1[o*12+3+k], d3w1[o*12+6+k], d3w1[o*12+9+k]);
  }
  if (tid < 4) sh_p2[tid] = make_float4(d2w2[tid*4+0], d2w2[tid*4+1], d2w2[tid*4+2], d2w2[tid*4+3]);
  float4 w2k[3][4]; loadConvW(d2w1, w2k);
  float m2, i2; finalizeStats(g_p2, b, INV_N1, m2, i2);
  __syncthreads();

  float sum = 0.f, sq = 0.f;
  for (int r = 0; r < 8; ++r){
    int a = warp + 8*r;
    float4 I0 = f4add(sb[a*DDW + lane],      x1b[a*DDW + lane]);
    float4 I1 = f4add(sb[a*DDW + lane + 32], x1b[a*DDW + lane + 32]);
    Taps it = makeTaps(I0, I1, lane);
    float t0[4], t1[4];
    #pragma unroll
    for (int o = 0; o < 4; o++){
      float y0 = dot4(w2k[0][o], it.m0) + dot4(w2k[1][o], I0) + dot4(w2k[2][o], it.p0);
      float y1 = dot4(w2k[0][o], it.m1) + dot4(w2k[1][o], I1) + dot4(w2k[2][o], it.p1);
      t0[o] = (y0 - m2)*i2;  t1[o] = (y1 - m2)*i2;
    }
    float4 tv0 = make_float4(t0[0], t0[1], t0[2], t0[3]);
    float4 tv1 = make_float4(t1[0], t1[1], t1[2], t1[3]);
    float4 xv0 = make_float4(geluf(dot4(sh_p2[0], tv0)), geluf(dot4(sh_p2[1], tv0)),
                             geluf(dot4(sh_p2[2], tv0)), geluf(dot4(sh_p2[3], tv0)));
    float4 xv1 = make_float4(geluf(dot4(sh_p2[0], tv1)), geluf(dot4(sh_p2[1], tv1)),
                             geluf(dot4(sh_p2[2], tv1)), geluf(dot4(sh_p2[3], tv1)));
    x2b[a*DDW + lane]      = xv0;
    x2b[a*DDW + lane + 32] = xv1;
    Taps xt = makeTaps(xv0, xv1, lane);
    float4 U0m = f4add(it.m0, xt.m0), U0c = f4add(I0, xv0), U0p = f4add(it.p0, xt.p0);
    float4 U1m = f4add(it.m1, xt.m1), U1c = f4add(I1, xv1), U1p = f4add(it.p1, xt.p1);
    #pragma unroll
    for (int o = 0; o < 4; o++){
      float y0 = dot4(sh_w3[o], U0m) + dot4(sh_w3[4+o], U0c) + dot4(sh_w3[8+o], U0p);
      float y1 = dot4(sh_w3[o], U1m) + dot4(sh_w3[4+o], U1c) + dot4(sh_w3[8+o], U1p);
      sum += y0 + y1; sq = fmaf(y0, y0, fmaf(y1, y1, sq));
    }
  }
  blockReduceStore(sum, sq, &g_p3[blockIdx.x]);
}

// ============ K3: x3 (regs) + zraw (phase-split) + cat stats ============
__global__ void __launch_bounds__(NTH, 2)
k_passD(const float* __restrict__ s, const float* __restrict__ d3w1,
        const float* __restrict__ d3w2, const float* __restrict__ cw,
        const float* __restrict__ c2w)
{
  __shared__ float2 sh_c2[16*4*32];    // [o][p][lane] = (c2w[d=lane], c2w[d=lane+32])
  __shared__ float  sh_cw[48];         // [p*12+c]
  __shared__ float4 sh_w3[12];
  __shared__ float4 sh_p3[4];
  const int b = blockIdx.x >> 3, chk = blockIdx.x & 7, tid = threadIdx.x;
  const int lane = tid & 31, warp = tid >> 5;
  const size_t off = (size_t)b*NPOS*4 + (size_t)chk*ROWS*DDW*4;
  const float4* sb  = reinterpret_cast<const float4*>(s + off);
  const float4* x1b = reinterpret_cast<const float4*>(g_x1 + off);
  const float4* x2b = reinterpret_cast<const float4*>(g_x2 + off);
  for (int k = tid; k < 2048; k += NTH){
    int l = k & 31, p = (k >> 5) & 3, o = k >> 7;
    sh_c2[k] = make_float2(c2w[o*256 + p*64 + l], c2w[o*256 + p*64 + l + 32]);
  }
  if (tid < 48) sh_cw[tid] = cw[tid];
  if (tid < 12){
    int k = tid >> 2, o = tid & 3;
    sh_w3[tid] = make_float4(d3w1[o*12+k], d3w1[o*12+3+k], d3w1[o*12+6+k], d3w1[o*12+9+k]);
  }
  if (tid < 4) sh_p3[tid] = make_float4(d3w2[tid*4+0], d3w2[tid*4+1], d3w2[tid*4+2], d3w2[tid*4+3]);
  float m3, i3; finalizeStats(g_p3, b, INV_N1, m3, i3);
  __syncthreads();

  float sum = 0.f, sq = 0.f;
  for (int g = 0; g < 2; ++g){
    float V[4][2][4];                  // [row][half][p]
    // -------- phase 1: 4 rows -> v[p] in registers --------
    #pragma unroll
    for (int r = 0; r < 4; ++r){
      int a = warp + 8*(4*g + r);
      float4 X0 = x1b[a*DDW + lane], X1 = x1b[a*DDW + lane + 32];
      float4 Y0 = x2b[a*DDW + lane], Y1 = x2b[a*DDW + lane + 32];
      float4 I0 = f4add(f4add(sb[a*DDW + lane],      X0), Y0);
      float4 I1 = f4add(f4add(sb[a*DDW + lane + 32], X1), Y1);
      Taps it = makeTaps(I0, I1, lane);
      float t0[4], t1[4];
      #pragma unroll
      for (int o = 0; o < 4; o++){
        float y0 = dot4(sh_w3[o], it.m0) + dot4(sh_w3[4+o], I0) + dot4(sh_w3[8+o], it.p0);
        float y1 = dot4(sh_w3[o], it.m1) + dot4(sh_w3[4+o], I1) + dot4(sh_w3[8+o], it.p1);
        t0[o] = (y0 - m3)*i3;  t1[o] = (y1 - m3)*i3;
      }
      float4 tv0 = make_float4(t0[0], t0[1], t0[2], t0[3]);
      float4 tv1 = make_float4(t1[0], t1[1], t1[2], t1[3]);
      float4 x30 = make_float4(geluf(dot4(sh_p3[0], tv0)), geluf(dot4(sh_p3[1], tv0)),
                               geluf(dot4(sh_p3[2], tv0)), geluf(dot4(sh_p3[3], tv0)));
      float4 x31 = make_float4(geluf(dot4(sh_p3[0], tv1)), geluf(dot4(sh_p3[1], tv1)),
                               geluf(dot4(sh_p3[2], tv1)), geluf(dot4(sh_p3[3], tv1)));
      // cat stats at both output positions
      sum += X0.x+X0.y+X0.z+X0.w + Y0.x+Y0.y+Y0.z+Y0.w + x30.x+x30.y+x30.z+x30.w;
      sum += X1.x+X1.y+X1.z+X1.w + Y1.x+Y1.y+Y1.z+Y1.w + x31.x+x31.y+x31.z+x31.w;
      sq = fmaf(X0.x,X0.x, fmaf(X0.y,X0.y, fmaf(X0.z,X0.z, fmaf(X0.w,X0.w, sq))));
      sq = fmaf(Y0.x,Y0.x, fmaf(Y0.y,Y0.y, fmaf(Y0.z,Y0.z, fmaf(Y0.w,Y0.w, sq))));
      sq = fmaf(x30.x,x30.x, fmaf(x30.y,x30.y, fmaf(x30.z,x30.z, fmaf(x30.w,x30.w, sq))));
      sq = fmaf(X1.x,X1.x, fmaf(X1.y,X1.y, fmaf(X1.z,X1.z, fmaf(X1.w,X1.w, sq))));
      sq = fmaf(Y1.x,Y1.x, fmaf(Y1.y,Y1.y, fmaf(Y1.z,Y1.z, fmaf(Y1.w,Y1.w, sq))));
      sq = fmaf(x31.x,x31.x, fmaf(x31.y,x31.y, fmaf(x31.z,x31.z, fmaf(x31.w,x31.w, sq))));
      #pragma unroll
      for (int p = 0; p < 4; p++){
        const float* cwp = sh_cw + p*12;
        float a0 = cwp[0]*X0.x + cwp[1]*X0.y + cwp[2]*X0.z + cwp[3]*X0.w;
        a0 = fmaf(cwp[4], Y0.x, fmaf(cwp[5], Y0.y, fmaf(cwp[6], Y0.z, fmaf(cwp[7], Y0.w, a0))));
        a0 = fmaf(cwp[8], x30.x, fmaf(cwp[9], x30.y, fmaf(cwp[10], x30.z, fmaf(cwp[11], x30.w, a0))));
        V[r][0][p] = a0;
        float a1 = cwp[0]*X1.x + cwp[1]*X1.y + cwp[2]*X1.z + cwp[3]*X1.w;
        a1 = fmaf(cwp[4], Y1.x, fmaf(cwp[5], Y1.y, fmaf(cwp[6], Y1.z, fmaf(cwp[7], Y1.w, a1))));
        a1 = fmaf(cwp[8], x31.x, fmaf(cwp[9], x31.y, fmaf(cwp[10], x31.z, fmaf(cwp[11], x31.w, a1))));
        V[r][1][p] = a1;
      }
    }
    // -------- phase 2: z[o] for the 4 rows; c2w read once per o --------
    #pragma unroll
    for (int o = 0; o < 16; ++o){
      float2 wv[4];
      #pragma unroll
      for (int p = 0; p < 4; p++)
        wv[p] = sh_c2[(o*4 + p)*32 + lane];
      float acc[4];
      #pragma unroll
      for (int r = 0; r < 4; ++r){
        float a0 = 0.f;
        #pragma unroll
        for (int p = 0; p < 4; p++)
          a0 = fmaf(wv[p].x, V[r][0][p], fmaf(wv[p].y, V[r][1][p], a0));
        acc[r] = a0;
      }
      // split-butterfly: 4 values over 32 lanes in 6 shuffles
      const bool b4 = (lane & 16) != 0, b3 = (lane & 8) != 0;
      float s0 = b4 ? acc[2] : acc[0];
      float s1 = b4 ? acc[3] : acc[1];
      s0 += __shfl_xor_sync(FULLM, b4 ? acc[0] : acc[2], 16);
      s1 += __shfl_xor_sync(FULLM, b4 ? acc[1] : acc[3], 16);
      float sv = b3 ? s1 : s0;
      sv += __shfl_xor_sync(FULLM, b3 ? s0 : s1, 8);
      sv += __shfl_xor_sync(FULLM, sv, 4);
      sv += __shfl_xor_sync(FULLM, sv, 2);
      sv += __shfl_xor_sync(FULLM, sv, 1);
      if ((lane & 7) == 0){
        int r = ((lane >> 4) << 1) | ((lane >> 3) & 1);
        int ag = chk*ROWS + warp + 8*(4*g + r);
        g_z[((size_t)b*AA + ag)*16 + o] = sv;
      }
    }
  }
  blockReduceStore(sum, sq, &g_p4[blockIdx.x]);
}

// ============ K4: affine-correct zraw -> LN -> +w -> 1x1(17->1) -> LN -> out ============
__global__ void __launch_bounds__(NTH)
k_final(const float* __restrict__ w, const float* __restrict__ cw,
        const float* __restrict__ c2w, const float* __restrict__ c3w,
        float* __restrict__ out)
{
  __shared__ float sh_z[AA*17];
  __shared__ float sh_red[18];
  __shared__ float sh_c3[17];
  __shared__ float sh_K[16];
  const int b = blockIdx.x, tid = threadIdx.x;
  if (tid < 17) sh_c3[tid] = c3w[tid];
  if (tid < 16){
    float csum[4];
    #pragma unroll
    for (int p = 0; p < 4; p++){
      float t = 0.f;
      #pragma unroll
      for (int c = 0; c < 12; c++) t += cw[p*12 + c];
      csum[p] = t;
    }
    float kk = 0.f;
    #pragma unroll
    for (int p = 0; p < 4; p++){
      const float* cb = c2w + tid*256 + p*64;
      float t = 0.f;
      for (int d = 0; d < 64; d++) t += cb[d];
      kk = fmaf(csum[p], t, kk);
    }
    sh_K[tid] = kk;
  }
  float mc, icat; finalizeStats(g_p4, b, INV_N12, mc, icat);
  __syncthreads();

  const float4* zsrc = reinterpret_cast<const float4*>(g_z + (size_t)b*AA*16);
  float sz = 0.f, qz = 0.f;
  for (int idx = tid; idx < AA*4; idx += NTH){
    float4 v = zsrc[idx];
    int a = idx >> 2, o4 = (idx & 3)*4;
    v.x = icat*(v.x - mc*sh_K[o4+0]);
    v.y = icat*(v.y - mc*sh_K[o4+1]);
    v.z = icat*(v.z - mc*sh_K[o4+2]);
    v.w = icat*(v.w - mc*sh_K[o4+3]);
    float* dst = sh_z + a*17 + o4;
    dst[0] = v.x; dst[1] = v.y; dst[2] = v.z; dst[3] = v.w;
    sz += v.x+v.y+v.z+v.w;
    qz = fmaf(v.x,v.x, fmaf(v.y,v.y, fmaf(v.z,v.z, fmaf(v.w,v.w, qz))));
  }
  blockReduce2(sz, qz, sh_red);
  const float invN4 = 1.f/(16.f*(float)AA);
  float m4 = sz*invN4;
  float i4 = rsqrtf(fmaf(-m4, m4, qz*invN4) + EPSF);

  float rv[2]; float sr = 0.f, qr = 0.f;
  #pragma unroll
  for (int j = 0; j < 2; j++){
    int a = tid + j*NTH;
    float r = sh_c3[16]*w[(size_t)b*AA + a];
    const float* zr = sh_z + a*17;
    #pragma unroll
    for (int o = 0; o < 16; o++)
      r = fmaf(sh_c3[o], (zr[o] - m4)*i4, r);
    rv[j] = r; sr += r; qr = fmaf(r, r, qr);
  }
  blockReduce2(sr, qr, sh_red);
  float m5 = sr*(1.f/(float)AA);
  float i5 = rsqrtf(fmaf(-m5, m5, qr*(1.f/(float)AA)) + EPSF);
  #pragma unroll
  for (int j = 0; j < 2; j++)
    out[(size_t)b*AA + tid + j*NTH] = (rv[j] - m5)*i5;
}

extern "C" void kernel_launch(void* const* d_in, const int* in_sizes, int n_in,
                              void* d_out, int out_size)
{
  (void)in_sizes; (void)n_in; (void)out_size;
  const float* s    = (const float*)d_in[0];
  const float* w    = (const float*)d_in[1];
  const float* d1w1 = (const float*)d_in[2];
  const float* d1w2 = (const float*)d_in[3];
  const float* d2w1 = (const float*)d_in[4];
  const float* d2w2 = (const float*)d_in[5];
  const float* d3w1 = (const float*)d_in[6];
  const float* d3w2 = (const float*)d_in[7];
  const float* cw   = (const float*)d_in[8];
  const float* c2w  = (const float*)d_in[9];
  const float* c3w  = (const float*)d_in[10];
  float* out = (float*)d_out;

  k_statsA<<<BB*CH, NTH>>>(s, d1w1);
  k_passB <<<BB*CH, NTH>>>(s, d1w1, d1w2, d2w1);
  k_passC <<<BB*CH, NTH>>>(s, d2w1, d2w2, d3w1);
  k_passD <<<BB*CH, NTH>>>(s, d3w1, d3w2, cw, c2w);
  k_final <<<BB,    NTH>>>(w, cw, c2w, c3w, out);
}